// round 9
// baseline (speedup 1.0000x reference)
#include <cuda_runtime.h>
#include <cuda_bf16.h>
#include <math.h>
#include <stdint.h>

// Problem constants
#define BB 4
#define TT 2048
#define CC 1024
#define HH 16
#define DD 64
#define MM (BB*TT)   // 8192 rows

// ---------------------------------------------------------------------------
// Scratch (__device__ globals; no allocation allowed)
// ---------------------------------------------------------------------------
__device__ __nv_bfloat16 g_xhi[(size_t)MM * CC];
__device__ __nv_bfloat16 g_xlo[(size_t)MM * CC];
__device__ __nv_bfloat16 g_qh[(size_t)MM * CC];   // (b,h,t,d)
__device__ __nv_bfloat16 g_ql[(size_t)MM * CC];
__device__ __nv_bfloat16 g_kh[(size_t)MM * CC];
__device__ __nv_bfloat16 g_kl[(size_t)MM * CC];
__device__ __nv_bfloat16 g_vh[(size_t)MM * CC];
__device__ __nv_bfloat16 g_vl[(size_t)MM * CC];
__device__ __nv_bfloat16 g_yh[(size_t)MM * CC];   // (b,t,c)
__device__ __nv_bfloat16 g_yl[(size_t)MM * CC];
__device__ __nv_bfloat16 g_wq_hi[(size_t)CC * CC];
__device__ __nv_bfloat16 g_wq_lo[(size_t)CC * CC];
__device__ __nv_bfloat16 g_wk_hi[(size_t)CC * CC];
__device__ __nv_bfloat16 g_wk_lo[(size_t)CC * CC];
__device__ __nv_bfloat16 g_wv_hi[(size_t)CC * CC];
__device__ __nv_bfloat16 g_wv_lo[(size_t)CC * CC];
__device__ __nv_bfloat16 g_wp_hi[(size_t)CC * CC];
__device__ __nv_bfloat16 g_wp_lo[(size_t)CC * CC];

// ---------------------------------------------------------------------------
// Helpers: cp.async, ldmatrix, mma.sync (baseline PTX only)
// ---------------------------------------------------------------------------
__device__ __forceinline__ uint32_t smem_u32(const void* p) {
    uint32_t a;
    asm("{ .reg .u64 t; cvta.to.shared.u64 t, %1; cvt.u32.u64 %0, t; }" : "=r"(a) : "l"(p));
    return a;
}
#define CP_ASYNC16(dst, src) \
    asm volatile("cp.async.cg.shared.global [%0], [%1], 16;" :: "r"(dst), "l"(src) : "memory")
#define CP_COMMIT() asm volatile("cp.async.commit_group;" ::: "memory")
#define CP_WAIT0()  asm volatile("cp.async.wait_group 0;" ::: "memory")
#define CP_WAIT1()  asm volatile("cp.async.wait_group 1;" ::: "memory")
#define CP_WAIT2()  asm volatile("cp.async.wait_group 2;" ::: "memory")

#define LDM_X4(r0, r1, r2, r3, a) \
    asm volatile("ldmatrix.sync.aligned.m8n8.x4.shared.b16 {%0,%1,%2,%3}, [%4];" \
        : "=r"(r0), "=r"(r1), "=r"(r2), "=r"(r3) : "r"(a))
#define LDM_X4T(r0, r1, r2, r3, a) \
    asm volatile("ldmatrix.sync.aligned.m8n8.x4.trans.shared.b16 {%0,%1,%2,%3}, [%4];" \
        : "=r"(r0), "=r"(r1), "=r"(r2), "=r"(r3) : "r"(a))

#define MMA_BF16(acc, a, b0, b1) \
    asm volatile("mma.sync.aligned.m16n8k16.row.col.f32.bf16.bf16.f32 " \
        "{%0,%1,%2,%3},{%4,%5,%6,%7},{%8,%9},{%0,%1,%2,%3};" \
        : "+f"((acc)[0]), "+f"((acc)[1]), "+f"((acc)[2]), "+f"((acc)[3]) \
        : "r"((a)[0]), "r"((a)[1]), "r"((a)[2]), "r"((a)[3]), "r"(b0), "r"(b1))

#define SWZ(x) ((x) ^ (((x) >> 3) & 0x70))

__device__ __forceinline__ uint32_t pack_bf16(float x, float y) {
    __nv_bfloat162 h = __float22bfloat162_rn(make_float2(x, y));
    return *(uint32_t*)&h;
}
__device__ __forceinline__ float2 unpack_bf16(uint32_t u) {
    __nv_bfloat162 h = *(__nv_bfloat162*)&u;
    return __bfloat1622float2(h);
}

// ---------------------------------------------------------------------------
// Fused fp32 -> (bf16 hi, bf16 lo) conversion for x + 4 weight matrices.
// ---------------------------------------------------------------------------
#define XN4 (MM * CC / 4)
#define WN4 (CC * CC / 4)

__global__ void __launch_bounds__(256) cvt_all(
    const float* __restrict__ x,
    const float* __restrict__ Wq, const float* __restrict__ Wk,
    const float* __restrict__ Wv, const float* __restrict__ Wp,
    __nv_bfloat16* __restrict__ xhi, __nv_bfloat16* __restrict__ xlo,
    __nv_bfloat16* __restrict__ wqh, __nv_bfloat16* __restrict__ wql,
    __nv_bfloat16* __restrict__ wkh, __nv_bfloat16* __restrict__ wkl,
    __nv_bfloat16* __restrict__ wvh, __nv_bfloat16* __restrict__ wvl,
    __nv_bfloat16* __restrict__ wph, __nv_bfloat16* __restrict__ wpl)
{
    int i = blockIdx.x * blockDim.x + threadIdx.x;
    const float* src;
    __nv_bfloat16 *hi, *lo;
    int off;
    if (i < XN4) { src = x; hi = xhi; lo = xlo; off = i; }
    else {
        int j = i - XN4;
        const int w = j / WN4;
        off = j - w * WN4;
        if (w == 0)      { src = Wq; hi = wqh; lo = wql; }
        else if (w == 1) { src = Wk; hi = wkh; lo = wkl; }
        else if (w == 2) { src = Wv; hi = wvh; lo = wvl; }
        else             { src = Wp; hi = wph; lo = wpl; }
    }
    float4 v = ((const float4*)src)[off];
    __nv_bfloat16 h0 = __float2bfloat16(v.x);
    __nv_bfloat16 h1 = __float2bfloat16(v.y);
    __nv_bfloat16 h2 = __float2bfloat16(v.z);
    __nv_bfloat16 h3 = __float2bfloat16(v.w);
    __nv_bfloat16 l0 = __float2bfloat16(v.x - __bfloat162float(h0));
    __nv_bfloat16 l1 = __float2bfloat16(v.y - __bfloat162float(h1));
    __nv_bfloat16 l2 = __float2bfloat16(v.z - __bfloat162float(h2));
    __nv_bfloat16 l3 = __float2bfloat16(v.w - __bfloat162float(h3));
    ((__nv_bfloat162*)hi)[2 * off + 0] = __nv_bfloat162(h0, h1);
    ((__nv_bfloat162*)hi)[2 * off + 1] = __nv_bfloat162(h2, h3);
    ((__nv_bfloat162*)lo)[2 * off + 0] = __nv_bfloat162(l0, l1);
    ((__nv_bfloat162*)lo)[2 * off + 1] = __nv_bfloat162(l2, l3);
}

// ---------------------------------------------------------------------------
// mma.sync GEMM core: out(M,N) = (A @ B^T + bias) * scale, hi/lo bf16 3-term.
// CTA 128x128, 8 warps (2m x 4n) of 64x32, K-chunk 32, 3-stage cp.async.
// MODE 0: fp32 row-major output. MODE 1: bf16 hi/lo head-split output.
// ---------------------------------------------------------------------------
#define KC 32
#define NCH (CC / KC)
#define STG_A 16384
#define STG_BYTES 32768
#define GEMM_SMEM (3 * STG_BYTES)

template<int MODE>
__device__ __forceinline__ void gemm_core(
    char* smem,
    const __nv_bfloat16* __restrict__ Ahi, const __nv_bfloat16* __restrict__ Alo,
    const __nv_bfloat16* __restrict__ Bhi, const __nv_bfloat16* __restrict__ Blo,
    const float* __restrict__ bias, float* __restrict__ outF,
    __nv_bfloat16* __restrict__ outH, __nv_bfloat16* __restrict__ outL,
    float scale)
{
    const uint32_t sbase = smem_u32(smem);
    const int tid = threadIdx.x;
    const int wid = tid >> 5;
    const int lid = tid & 31;
    const int m0 = blockIdx.y * 128;
    const int n0 = blockIdx.x * 128;
    const int wm = (wid & 1) * 64;
    const int wn = (wid >> 1) * 32;

    uint32_t l_dst[8];
    const __nv_bfloat16* l_src[8];
    #pragma unroll
    for (int it = 0; it < 8; ++it) {
        const int u = it * 256 + tid;
        const bool isA = u < 1024;
        const int v = isA ? u : u - 1024;
        const int r = v >> 3, sub = v & 7;
        const int cbyte = (sub & 3) * 16 + (sub >> 2) * 64;
        l_dst[it] = sbase + (isA ? 0 : STG_A) + SWZ(r * 128 + cbyte);
        const __nv_bfloat16* basep = isA ? ((sub < 4) ? Ahi : Alo)
                                         : ((sub < 4) ? Bhi : Blo);
        const int row = isA ? (m0 + r) : (n0 + r);
        l_src[it] = basep + (size_t)row * CC + (sub & 3) * 8;
    }

    uint32_t a_off[4][2], b_off[2][2];
    #pragma unroll
    for (int mi = 0; mi < 4; ++mi)
        #pragma unroll
        for (int s = 0; s < 2; ++s) {
            const int r = wm + mi * 16 + (lid & 15);
            const int cb = s * 32 + ((lid >> 4) << 4);
            a_off[mi][s] = SWZ(r * 128 + cb);
        }
    #pragma unroll
    for (int pr = 0; pr < 2; ++pr)
        #pragma unroll
        for (int s = 0; s < 2; ++s) {
            const int r = wn + pr * 16 + (lid & 7) + ((lid >> 4) << 3);
            const int cb = s * 32 + (((lid >> 3) & 1) << 4);
            b_off[pr][s] = SWZ(r * 128 + cb);
        }

    float acc[4][4][4];
    #pragma unroll
    for (int i = 0; i < 4; ++i)
        #pragma unroll
        for (int j = 0; j < 4; ++j)
            #pragma unroll
            for (int e = 0; e < 4; ++e) acc[i][j][e] = 0.f;

    #pragma unroll
    for (int c = 0; c < 2; ++c) {
        const uint32_t so = c * STG_BYTES;
        #pragma unroll
        for (int it = 0; it < 8; ++it)
            CP_ASYNC16(l_dst[it] + so, l_src[it] + c * KC);
        CP_COMMIT();
    }

    for (int ch = 0; ch < NCH; ++ch) {
        const int nxt = ch + 2;
        if (nxt < NCH) {
            const uint32_t so = (nxt % 3) * STG_BYTES;
            #pragma unroll
            for (int it = 0; it < 8; ++it)
                CP_ASYNC16(l_dst[it] + so, l_src[it] + nxt * KC);
        }
        CP_COMMIT();
        CP_WAIT2();
        __syncthreads();

        const uint32_t Ab = sbase + (ch % 3) * STG_BYTES;
        const uint32_t Bb = Ab + STG_A;

        #pragma unroll
        for (int s = 0; s < 2; ++s) {
            uint32_t ah[4][4], al[4][4];
            #pragma unroll
            for (int mi = 0; mi < 4; ++mi) {
                const uint32_t ad = Ab + a_off[mi][s];
                LDM_X4(ah[mi][0], ah[mi][1], ah[mi][2], ah[mi][3], ad);
                LDM_X4(al[mi][0], al[mi][1], al[mi][2], al[mi][3], ad ^ 64u);
            }
            #pragma unroll
            for (int pr = 0; pr < 2; ++pr) {
                uint32_t bh[4], bl[4];
                const uint32_t bd = Bb + b_off[pr][s];
                LDM_X4(bh[0], bh[1], bh[2], bh[3], bd);
                LDM_X4(bl[0], bl[1], bl[2], bl[3], bd ^ 64u);
                #pragma unroll
                for (int mi = 0; mi < 4; ++mi) {
                    MMA_BF16(acc[mi][2 * pr + 0], ah[mi], bh[0], bh[1]);
                    MMA_BF16(acc[mi][2 * pr + 1], ah[mi], bh[2], bh[3]);
                    MMA_BF16(acc[mi][2 * pr + 0], al[mi], bh[0], bh[1]);
                    MMA_BF16(acc[mi][2 * pr + 1], al[mi], bh[2], bh[3]);
                    MMA_BF16(acc[mi][2 * pr + 0], ah[mi], bl[0], bl[1]);
                    MMA_BF16(acc[mi][2 * pr + 1], ah[mi], bl[2], bl[3]);
                }
            }
        }
        __syncthreads();
    }

    #pragma unroll
    for (int nj = 0; nj < 4; ++nj) {
        const int n = n0 + wn + nj * 8 + (lid & 3) * 2;
        const float bx = bias[n], by = bias[n + 1];
        #pragma unroll
        for (int mi = 0; mi < 4; ++mi) {
            #pragma unroll
            for (int half = 0; half < 2; ++half) {
                const int m = m0 + wm + mi * 16 + (lid >> 2) + half * 8;
                const float rx = (acc[mi][nj][2 * half + 0] + bx) * scale;
                const float ry = (acc[mi][nj][2 * half + 1] + by) * scale;
                if (MODE == 0) {
                    float2 r; r.x = rx; r.y = ry;
                    *(float2*)(outF + (size_t)m * CC + n) = r;
                } else {
                    const int b = m >> 11, t = m & (TT - 1);
                    const int h = n >> 6, d = n & 63;
                    const size_t idx = (((size_t)b * HH + h) * TT + t) * DD + d;
                    const uint32_t hp = pack_bf16(rx, ry);
                    const float2 hv = unpack_bf16(hp);
                    const uint32_t lp = pack_bf16(rx - hv.x, ry - hv.y);
                    *(uint32_t*)(outH + idx) = hp;
                    *(uint32_t*)(outL + idx) = lp;
                }
            }
        }
    }
}

// QKV fused: blockIdx.z selects which projection this CTA computes.
__global__ void __launch_bounds__(256, 2) qkv_gemm(
    const __nv_bfloat16* __restrict__ xhi, const __nv_bfloat16* __restrict__ xlo,
    const __nv_bfloat16* __restrict__ wqh, const __nv_bfloat16* __restrict__ wql,
    const __nv_bfloat16* __restrict__ wkh, const __nv_bfloat16* __restrict__ wkl,
    const __nv_bfloat16* __restrict__ wvh, const __nv_bfloat16* __restrict__ wvl,
    const float* __restrict__ bq, const float* __restrict__ bk,
    const float* __restrict__ bv,
    __nv_bfloat16* __restrict__ qh, __nv_bfloat16* __restrict__ ql,
    __nv_bfloat16* __restrict__ kh, __nv_bfloat16* __restrict__ kl,
    __nv_bfloat16* __restrict__ vh, __nv_bfloat16* __restrict__ vl)
{
    extern __shared__ char smem[];
    const int z = blockIdx.z;
    const __nv_bfloat16* Bh = (z == 0) ? wqh : (z == 1) ? wkh : wvh;
    const __nv_bfloat16* Bl = (z == 0) ? wql : (z == 1) ? wkl : wvl;
    const float* bias = (z == 0) ? bq : (z == 1) ? bk : bv;
    __nv_bfloat16* oh = (z == 0) ? qh : (z == 1) ? kh : vh;
    __nv_bfloat16* ol = (z == 0) ? ql : (z == 1) ? kl : vl;
    const float scale = (z == 0) ? 0.125f : 1.0f;
    gemm_core<1>(smem, xhi, xlo, Bh, Bl, bias, nullptr, oh, ol, scale);
}

__global__ void __launch_bounds__(256, 2) proj_gemm(
    const __nv_bfloat16* __restrict__ yh, const __nv_bfloat16* __restrict__ yl,
    const __nv_bfloat16* __restrict__ wph, const __nv_bfloat16* __restrict__ wpl,
    const float* __restrict__ bp, float* __restrict__ out)
{
    extern __shared__ char smem[];
    gemm_core<0>(smem, yh, yl, wph, wpl, bp, out, nullptr, nullptr, 1.0f);
}

// ---------------------------------------------------------------------------
// Flash attention with mma.sync (bf16 hi/lo, fp32 softmax).
// CTA: 128 q-rows of one (b,h); 8 warps x 16 rows; kv tiles of 64.
// SMEM: Qhi 16K | Qlo 16K | stage{0,1}: Khi 8K, Klo 8K, Vhi 8K, Vlo 8K.
// ---------------------------------------------------------------------------
#define ATT_STG 32768
#define ATT_SMEM (32768 + 2 * ATT_STG)

__global__ void __launch_bounds__(256, 2) attn_mma(
    const __nv_bfloat16* __restrict__ qh, const __nv_bfloat16* __restrict__ ql,
    const __nv_bfloat16* __restrict__ kh, const __nv_bfloat16* __restrict__ kl,
    const __nv_bfloat16* __restrict__ vh, const __nv_bfloat16* __restrict__ vl,
    __nv_bfloat16* __restrict__ yhi, __nv_bfloat16* __restrict__ ylo)
{
    extern __shared__ char smem[];
    const uint32_t sb = smem_u32(smem);
    const int tid = threadIdx.x;
    const int wid = tid >> 5;
    const int lid = tid & 31;
    const int qt0 = blockIdx.x * 128;
    const int bh = blockIdx.y;
    const int wm = wid * 16;
    const size_t hb = (size_t)bh * TT * DD;

    const __nv_bfloat16* khp = kh + hb;
    const __nv_bfloat16* klp = kl + hb;
    const __nv_bfloat16* vhp = vh + hb;
    const __nv_bfloat16* vlp = vl + hb;

    #pragma unroll
    for (int it = 0; it < 8; ++it) {
        const int arr = it >> 2;
        const int v = ((it & 3) << 8) + tid;
        const int r = v >> 3, c = v & 7;
        const __nv_bfloat16* p = (arr ? ql : qh) + hb + (size_t)(qt0 + r) * DD + c * 8;
        CP_ASYNC16(sb + arr * 16384 + SWZ(r * 128 + c * 16), p);
    }
    CP_COMMIT();

    const int ntiles = 2 * blockIdx.x + 2;

    auto issue_kv = [&](int t, int stage) {
        const int kt0 = t * 64;
        #pragma unroll
        for (int it = 0; it < 8; ++it) {
            const int arr = it >> 1;
            const int v = ((it & 1) << 8) + tid;
            const int r = v >> 3, c = v & 7;
            const __nv_bfloat16* p = (arr == 0) ? khp : (arr == 1) ? klp
                                    : (arr == 2) ? vhp : vlp;
            CP_ASYNC16(sb + 32768 + stage * ATT_STG + arr * 8192 + SWZ(r * 128 + c * 16),
                       p + (size_t)(kt0 + r) * DD + c * 8);
        }
        CP_COMMIT();
    };

    issue_kv(0, 0);
    CP_WAIT1();
    __syncthreads();

    uint32_t aqh[4][4], aql[4][4];
    {
        const int ar = wm + (lid & 15);
        const int ac = (lid >> 4) << 4;
        #pragma unroll
        for (int s = 0; s < 4; ++s) {
            const uint32_t off = SWZ(ar * 128 + s * 32 + ac);
            LDM_X4(aqh[s][0], aqh[s][1], aqh[s][2], aqh[s][3], sb + off);
            LDM_X4(aql[s][0], aql[s][1], aql[s][2], aql[s][3], sb + 16384 + off);
        }
    }

    const int brow = (lid & 7) + ((lid >> 4) << 3);
    const int bcol = ((lid >> 3) & 1) << 4;
    const int vrow = (lid & 7) + (((lid >> 3) & 1) << 3);
    const int vcol = (lid >> 4) << 4;

    float oacc[8][4];
    #pragma unroll
    for (int j = 0; j < 8; ++j)
        #pragma unroll
        for (int e = 0; e < 4; ++e) oacc[j][e] = 0.f;
    float m0 = -1e30f, m1 = -1e30f, l0 = 0.f, l1 = 0.f;

    const int row0 = qt0 + wm + (lid >> 2);
    const int row1 = row0 + 8;
    const int colb = 2 * (lid & 3);

    for (int t = 0; t < ntiles; ++t) {
        if (t + 1 < ntiles) { issue_kv(t + 1, (t + 1) & 1); CP_WAIT1(); }
        else CP_WAIT0();
        __syncthreads();

        const int kt0 = t * 64;
        if (kt0 <= qt0 + wm + 15) {
            const uint32_t stg = sb + 32768 + (t & 1) * ATT_STG;
            const uint32_t kH = stg, kL = stg + 8192;
            const uint32_t vH = stg + 16384, vL = stg + 24576;

            float sacc[8][4];
            #pragma unroll
            for (int j = 0; j < 8; ++j)
                #pragma unroll
                for (int e = 0; e < 4; ++e) sacc[j][e] = 0.f;

            #pragma unroll
            for (int s = 0; s < 4; ++s) {
                #pragma unroll
                for (int pr = 0; pr < 4; ++pr) {
                    const uint32_t boff = SWZ((pr * 16 + brow) * 128 + s * 32 + bcol);
                    uint32_t bh0, bh1, bh2, bh3, bl0, bl1, bl2, bl3;
                    LDM_X4(bh0, bh1, bh2, bh3, kH + boff);
                    LDM_X4(bl0, bl1, bl2, bl3, kL + boff);
                    MMA_BF16(sacc[2 * pr + 0], aqh[s], bh0, bh1);
                    MMA_BF16(sacc[2 * pr + 0], aql[s], bh0, bh1);
                    MMA_BF16(sacc[2 * pr + 0], aqh[s], bl0, bl1);
                    MMA_BF16(sacc[2 * pr + 1], aqh[s], bh2, bh3);
                    MMA_BF16(sacc[2 * pr + 1], aql[s], bh2, bh3);
                    MMA_BF16(sacc[2 * pr + 1], aqh[s], bl2, bl3);
                }
            }

            if (kt0 + 64 > qt0 + wm) {
                #pragma unroll
                for (int j = 0; j < 8; ++j) {
                    const int c0 = kt0 + j * 8 + colb;
                    if (c0 > row0)     sacc[j][0] = -1e30f;
                    if (c0 + 1 > row0) sacc[j][1] = -1e30f;
                    if (c0 > row1)     sacc[j][2] = -1e30f;
                    if (c0 + 1 > row1) sacc[j][3] = -1e30f;
                }
            }

            float mx0 = -1e30f, mx1 = -1e30f;
            #pragma unroll
            for (int j = 0; j < 8; ++j) {
                mx0 = fmaxf(mx0, fmaxf(sacc[j][0], sacc[j][1]));
                mx1 = fmaxf(mx1, fmaxf(sacc[j][2], sacc[j][3]));
            }
            mx0 = fmaxf(mx0, __shfl_xor_sync(0xffffffffu, mx0, 1));
            mx0 = fmaxf(mx0, __shfl_xor_sync(0xffffffffu, mx0, 2));
            mx1 = fmaxf(mx1, __shfl_xor_sync(0xffffffffu, mx1, 1));
            mx1 = fmaxf(mx1, __shfl_xor_sync(0xffffffffu, mx1, 2));
            const float mn0 = fmaxf(m0, mx0), mn1 = fmaxf(m1, mx1);
            const float al0 = __expf(m0 - mn0), al1 = __expf(m1 - mn1);
            m0 = mn0; m1 = mn1;

            float rs0 = 0.f, rs1 = 0.f;
            #pragma unroll
            for (int j = 0; j < 8; ++j) {
                sacc[j][0] = __expf(sacc[j][0] - m0);
                sacc[j][1] = __expf(sacc[j][1] - m0);
                sacc[j][2] = __expf(sacc[j][2] - m1);
                sacc[j][3] = __expf(sacc[j][3] - m1);
                rs0 += sacc[j][0] + sacc[j][1];
                rs1 += sacc[j][2] + sacc[j][3];
            }
            rs0 += __shfl_xor_sync(0xffffffffu, rs0, 1);
            rs0 += __shfl_xor_sync(0xffffffffu, rs0, 2);
            rs1 += __shfl_xor_sync(0xffffffffu, rs1, 1);
            rs1 += __shfl_xor_sync(0xffffffffu, rs1, 2);
            l0 = l0 * al0 + rs0;
            l1 = l1 * al1 + rs1;
            #pragma unroll
            for (int j = 0; j < 8; ++j) {
                oacc[j][0] *= al0; oacc[j][1] *= al0;
                oacc[j][2] *= al1; oacc[j][3] *= al1;
            }

            #pragma unroll
            for (int kk = 0; kk < 4; ++kk) {
                const int j0 = 2 * kk, j1 = j0 + 1;
                uint32_t ph[4], pl[4];
                {
                    const uint32_t h0 = pack_bf16(sacc[j0][0], sacc[j0][1]);
                    const uint32_t h1 = pack_bf16(sacc[j0][2], sacc[j0][3]);
                    const uint32_t h2 = pack_bf16(sacc[j1][0], sacc[j1][1]);
                    const uint32_t h3 = pack_bf16(sacc[j1][2], sacc[j1][3]);
                    ph[0] = h0; ph[1] = h1; ph[2] = h2; ph[3] = h3;
                    const float2 f0 = unpack_bf16(h0), f1 = unpack_bf16(h1);
                    const float2 f2 = unpack_bf16(h2), f3 = unpack_bf16(h3);
                    pl[0] = pack_bf16(sacc[j0][0] - f0.x, sacc[j0][1] - f0.y);
                    pl[1] = pack_bf16(sacc[j0][2] - f1.x, sacc[j0][3] - f1.y);
                    pl[2] = pack_bf16(sacc[j1][0] - f2.x, sacc[j1][1] - f2.y);
                    pl[3] = pack_bf16(sacc[j1][2] - f3.x, sacc[j1][3] - f3.y);
                }
                #pragma unroll
                for (int dd = 0; dd < 4; ++dd) {
                    const uint32_t voff = SWZ((kk * 16 + vrow) * 128 + dd * 32 + vcol);
                    uint32_t vh0, vh1, vh2, vh3, vl0, vl1, vl2, vl3;
                    LDM_X4T(vh0, vh1, vh2, vh3, vH + voff);
                    LDM_X4T(vl0, vl1, vl2, vl3, vL + voff);
                    MMA_BF16(oacc[2 * dd + 0], ph, vh0, vh1);
                    MMA_BF16(oacc[2 * dd + 0], pl, vh0, vh1);
                    MMA_BF16(oacc[2 * dd + 0], ph, vl0, vl1);
                    MMA_BF16(oacc[2 * dd + 1], ph, vh2, vh3);
                    MMA_BF16(oacc[2 * dd + 1], pl, vh2, vh3);
                    MMA_BF16(oacc[2 * dd + 1], ph, vl2, vl3);
                }
            }
        }
        __syncthreads();
    }

    const int b = bh >> 4, h = bh & 15;
    const float inv0 = 1.f / l0, inv1 = 1.f / l1;
    #pragma unroll
    for (int j = 0; j < 8; ++j) {
        const int d = j * 8 + colb;
        const float o0 = oacc[j][0] * inv0, o1 = oacc[j][1] * inv0;
        const float o2 = oacc[j][2] * inv1, o3 = oacc[j][3] * inv1;
        const size_t i0 = ((size_t)b * TT + row0) * CC + h * DD + d;
        const size_t i1 = ((size_t)b * TT + row1) * CC + h * DD + d;
        const uint32_t h0 = pack_bf16(o0, o1);
        const float2 f0 = unpack_bf16(h0);
        const uint32_t lo0 = pack_bf16(o0 - f0.x, o1 - f0.y);
        const uint32_t h1 = pack_bf16(o2, o3);
        const float2 f1 = unpack_bf16(h1);
        const uint32_t lo1 = pack_bf16(o2 - f1.x, o3 - f1.y);
        *(uint32_t*)(yhi + i0) = h0;
        *(uint32_t*)(ylo + i0) = lo0;
        *(uint32_t*)(yhi + i1) = h1;
        *(uint32_t*)(ylo + i1) = lo1;
    }
}

// ---------------------------------------------------------------------------
// Launch
// ---------------------------------------------------------------------------
extern "C" void kernel_launch(void* const* d_in, const int* in_sizes, int n_in,
                              void* d_out, int out_size)
{
    (void)in_sizes; (void)n_in; (void)out_size;
    const float* x  = (const float*)d_in[0];
    const float* Wk = (const float*)d_in[1];
    const float* bk = (const float*)d_in[2];
    const float* Wq = (const float*)d_in[3];
    const float* bq = (const float*)d_in[4];
    const float* Wv = (const float*)d_in[5];
    const float* bv = (const float*)d_in[6];
    const float* Wp = (const float*)d_in[7];
    const float* bp = (const float*)d_in[8];
    float* out = (float*)d_out;

    __nv_bfloat16 *xhi, *xlo, *qh, *ql, *kh, *kl, *vh, *vl, *yh, *yl;
    __nv_bfloat16 *wqh, *wql, *wkh, *wkl, *wvh, *wvl, *wph, *wpl;
    cudaGetSymbolAddress((void**)&xhi, g_xhi);
    cudaGetSymbolAddress((void**)&xlo, g_xlo);
    cudaGetSymbolAddress((void**)&qh, g_qh);
    cudaGetSymbolAddress((void**)&ql, g_ql);
    cudaGetSymbolAddress((void**)&kh, g_kh);
    cudaGetSymbolAddress((void**)&kl, g_kl);
    cudaGetSymbolAddress((void**)&vh, g_vh);
    cudaGetSymbolAddress((void**)&vl, g_vl);
    cudaGetSymbolAddress((void**)&yh, g_yh);
    cudaGetSymbolAddress((void**)&yl, g_yl);
    cudaGetSymbolAddress((void**)&wqh, g_wq_hi);
    cudaGetSymbolAddress((void**)&wql, g_wq_lo);
    cudaGetSymbolAddress((void**)&wkh, g_wk_hi);
    cudaGetSymbolAddress((void**)&wkl, g_wk_lo);
    cudaGetSymbolAddress((void**)&wvh, g_wv_hi);
    cudaGetSymbolAddress((void**)&wvl, g_wv_lo);
    cudaGetSymbolAddress((void**)&wph, g_wp_hi);
    cudaGetSymbolAddress((void**)&wpl, g_wp_lo);

    cvt_all<<<(XN4 + 4 * WN4 + 255) / 256, 256>>>(
        x, Wq, Wk, Wv, Wp, xhi, xlo, wqh, wql, wkh, wkl, wvh, wvl, wph, wpl);

    cudaFuncSetAttribute(qkv_gemm, cudaFuncAttributeMaxDynamicSharedMemorySize, GEMM_SMEM);
    cudaFuncSetAttribute(proj_gemm, cudaFuncAttributeMaxDynamicSharedMemorySize, GEMM_SMEM);
    cudaFuncSetAttribute(attn_mma, cudaFuncAttributeMaxDynamicSharedMemorySize, ATT_SMEM);

    qkv_gemm<<<dim3(CC / 128, MM / 128, 3), 256, GEMM_SMEM>>>(
        xhi, xlo, wqh, wql, wkh, wkl, wvh, wvl,
        bq, bk, bv, qh, ql, kh, kl, vh, vl);

    attn_mma<<<dim3(TT / 128, BB * HH), 256, ATT_SMEM>>>(qh, ql, kh, kl, vh, vl, yh, yl);

    proj_gemm<<<dim3(CC / 128, MM / 128), 256, GEMM_SMEM>>>(yh, yl, wph, wpl, bp, out);
}

// round 11
// speedup vs baseline: 3.1768x; 3.1768x over previous
#include <cuda_runtime.h>
#include <cuda_fp16.h>
#include <math.h>
#include <stdint.h>

// Problem constants
#define BB 4
#define TT 2048
#define CC 1024
#define HH 16
#define DD 64
#define MM (BB*TT)   // 8192 rows

// ---------------------------------------------------------------------------
// Scratch (__device__ globals; no allocation allowed) — all fp16 now
// ---------------------------------------------------------------------------
__device__ __half g_x[(size_t)MM * CC];
__device__ __half g_q[(size_t)MM * CC];   // (b,h,t,d), pre-scaled by 1/8
__device__ __half g_k[(size_t)MM * CC];
__device__ __half g_v[(size_t)MM * CC];
__device__ __half g_y[(size_t)MM * CC];   // (b,t,c)
__device__ __half g_wq[(size_t)CC * CC];
__device__ __half g_wk[(size_t)CC * CC];
__device__ __half g_wv[(size_t)CC * CC];
__device__ __half g_wp[(size_t)CC * CC];

// ---------------------------------------------------------------------------
// Helpers (baseline PTX only — no sm_103a-gated features)
// ---------------------------------------------------------------------------
__device__ __forceinline__ uint32_t smem_u32(const void* p) {
    uint32_t a;
    asm("{ .reg .u64 t; cvta.to.shared.u64 t, %1; cvt.u32.u64 %0, t; }" : "=r"(a) : "l"(p));
    return a;
}
#define CP_ASYNC16(dst, src) \
    asm volatile("cp.async.cg.shared.global [%0], [%1], 16;" :: "r"(dst), "l"(src) : "memory")
#define CP_COMMIT() asm volatile("cp.async.commit_group;" ::: "memory")
#define CP_WAIT0()  asm volatile("cp.async.wait_group 0;" ::: "memory")
#define CP_WAIT1()  asm volatile("cp.async.wait_group 1;" ::: "memory")
#define CP_WAIT2()  asm volatile("cp.async.wait_group 2;" ::: "memory")

#define LDM_X4(r0, r1, r2, r3, a) \
    asm volatile("ldmatrix.sync.aligned.m8n8.x4.shared.b16 {%0,%1,%2,%3}, [%4];" \
        : "=r"(r0), "=r"(r1), "=r"(r2), "=r"(r3) : "r"(a))
#define LDM_X4T(r0, r1, r2, r3, a) \
    asm volatile("ldmatrix.sync.aligned.m8n8.x4.trans.shared.b16 {%0,%1,%2,%3}, [%4];" \
        : "=r"(r0), "=r"(r1), "=r"(r2), "=r"(r3) : "r"(a))

#define MMA_F16(acc, a, b0, b1) \
    asm volatile("mma.sync.aligned.m16n8k16.row.col.f32.f16.f16.f32 " \
        "{%0,%1,%2,%3},{%4,%5,%6,%7},{%8,%9},{%0,%1,%2,%3};" \
        : "+f"((acc)[0]), "+f"((acc)[1]), "+f"((acc)[2]), "+f"((acc)[3]) \
        : "r"((a)[0]), "r"((a)[1]), "r"((a)[2]), "r"((a)[3]), "r"(b0), "r"(b1))

#define SWZ(x) ((x) ^ (((x) >> 3) & 0x70))

__device__ __forceinline__ uint32_t pack_h2(float x, float y) {
    __half2 h = __floats2half2_rn(x, y);
    return *(uint32_t*)&h;
}

// ---------------------------------------------------------------------------
// Fused fp32 -> fp16 conversion for x + 4 weight matrices.
// ---------------------------------------------------------------------------
#define XN4 (MM * CC / 4)
#define WN4 (CC * CC / 4)

__global__ void __launch_bounds__(256) cvt_all(
    const float* __restrict__ x,
    const float* __restrict__ Wq, const float* __restrict__ Wk,
    const float* __restrict__ Wv, const float* __restrict__ Wp,
    __half* __restrict__ xo,
    __half* __restrict__ wqo, __half* __restrict__ wko,
    __half* __restrict__ wvo, __half* __restrict__ wpo)
{
    int i = blockIdx.x * blockDim.x + threadIdx.x;
    const float* src;
    __half* dst;
    int off;
    if (i < XN4) { src = x; dst = xo; off = i; }
    else {
        int j = i - XN4;
        const int w = j / WN4;
        off = j - w * WN4;
        if (w == 0)      { src = Wq; dst = wqo; }
        else if (w == 1) { src = Wk; dst = wko; }
        else if (w == 2) { src = Wv; dst = wvo; }
        else             { src = Wp; dst = wpo; }
    }
    float4 v = ((const float4*)src)[off];
    ((__half2*)dst)[2 * off + 0] = __floats2half2_rn(v.x, v.y);
    ((__half2*)dst)[2 * off + 1] = __floats2half2_rn(v.z, v.w);
}

// ---------------------------------------------------------------------------
// mma.sync fp16 GEMM: out(M,N) = (A(M,K) @ B(N,K)^T + bias) * scale
// CTA 128x128, 8 warps (2m x 4n) of 64x32, K-chunk 64 halves (128B rows),
// 3-stage cp.async. MODE 0: fp32 row-major out. MODE 1: fp16 head-split out.
// ---------------------------------------------------------------------------
#define KC 64
#define NCH (CC / KC)        // 16
#define STG_A 16384          // 128 rows * 128B
#define STG_BYTES 32768
#define GEMM_SMEM (3 * STG_BYTES)

template<int MODE>
__device__ __forceinline__ void gemm_core(
    char* smem,
    const __half* __restrict__ A, const __half* __restrict__ B,
    const float* __restrict__ bias, float* __restrict__ outF,
    __half* __restrict__ outH, float scale)
{
    const uint32_t sbase = smem_u32(smem);
    const int tid = threadIdx.x;
    const int wid = tid >> 5;
    const int lid = tid & 31;
    const int m0 = blockIdx.y * 128;
    const int n0 = blockIdx.x * 128;
    const int wm = (wid & 1) * 64;
    const int wn = (wid >> 1) * 32;

    // 2048 16B units per chunk (A: 1024, B: 1024), 8 per thread
    uint32_t l_dst[8];
    const __half* l_src[8];
    #pragma unroll
    for (int it = 0; it < 8; ++it) {
        const int u = it * 256 + tid;
        const bool isA = u < 1024;
        const int v = isA ? u : u - 1024;
        const int r = v >> 3, c = v & 7;
        l_dst[it] = sbase + (isA ? 0 : STG_A) + SWZ(r * 128 + c * 16);
        const int row = isA ? (m0 + r) : (n0 + r);
        l_src[it] = (isA ? A : B) + (size_t)row * CC + c * 8;
    }

    uint32_t a_off[4][4], b_off[2][4];
    #pragma unroll
    for (int mi = 0; mi < 4; ++mi)
        #pragma unroll
        for (int s = 0; s < 4; ++s) {
            const int r = wm + mi * 16 + (lid & 15);
            const int cb = s * 32 + ((lid >> 4) << 4);
            a_off[mi][s] = SWZ(r * 128 + cb);
        }
    #pragma unroll
    for (int pr = 0; pr < 2; ++pr)
        #pragma unroll
        for (int s = 0; s < 4; ++s) {
            const int r = wn + pr * 16 + (lid & 7) + ((lid >> 4) << 3);
            const int cb = s * 32 + (((lid >> 3) & 1) << 4);
            b_off[pr][s] = SWZ(r * 128 + cb);
        }

    float acc[4][4][4];
    #pragma unroll
    for (int i = 0; i < 4; ++i)
        #pragma unroll
        for (int j = 0; j < 4; ++j)
            #pragma unroll
            for (int e = 0; e < 4; ++e) acc[i][j][e] = 0.f;

    #pragma unroll
    for (int c = 0; c < 2; ++c) {
        const uint32_t so = c * STG_BYTES;
        #pragma unroll
        for (int it = 0; it < 8; ++it)
            CP_ASYNC16(l_dst[it] + so, l_src[it] + c * KC);
        CP_COMMIT();
    }

    for (int ch = 0; ch < NCH; ++ch) {
        const int nxt = ch + 2;
        if (nxt < NCH) {
            const uint32_t so = (nxt % 3) * STG_BYTES;
            #pragma unroll
            for (int it = 0; it < 8; ++it)
                CP_ASYNC16(l_dst[it] + so, l_src[it] + nxt * KC);
        }
        CP_COMMIT();
        CP_WAIT2();
        __syncthreads();

        const uint32_t Ab = sbase + (ch % 3) * STG_BYTES;
        const uint32_t Bb = Ab + STG_A;

        #pragma unroll
        for (int s = 0; s < 4; ++s) {
            uint32_t ah[4][4];
            #pragma unroll
            for (int mi = 0; mi < 4; ++mi)
                LDM_X4(ah[mi][0], ah[mi][1], ah[mi][2], ah[mi][3], Ab + a_off[mi][s]);
            #pragma unroll
            for (int pr = 0; pr < 2; ++pr) {
                uint32_t b0, b1, b2, b3;
                LDM_X4(b0, b1, b2, b3, Bb + b_off[pr][s]);
                #pragma unroll
                for (int mi = 0; mi < 4; ++mi) {
                    MMA_F16(acc[mi][2 * pr + 0], ah[mi], b0, b1);
                    MMA_F16(acc[mi][2 * pr + 1], ah[mi], b2, b3);
                }
            }
        }
        __syncthreads();
    }

    #pragma unroll
    for (int nj = 0; nj < 4; ++nj) {
        const int n = n0 + wn + nj * 8 + (lid & 3) * 2;
        const float bx = bias[n], by = bias[n + 1];
        #pragma unroll
        for (int mi = 0; mi < 4; ++mi) {
            #pragma unroll
            for (int half = 0; half < 2; ++half) {
                const int m = m0 + wm + mi * 16 + (lid >> 2) + half * 8;
                const float rx = (acc[mi][nj][2 * half + 0] + bx) * scale;
                const float ry = (acc[mi][nj][2 * half + 1] + by) * scale;
                if (MODE == 0) {
                    float2 r; r.x = rx; r.y = ry;
                    *(float2*)(outF + (size_t)m * CC + n) = r;
                } else {
                    const int b = m >> 11, t = m & (TT - 1);
                    const int h = n >> 6, d = n & 63;
                    const size_t idx = (((size_t)b * HH + h) * TT + t) * DD + d;
                    *(uint32_t*)(outH + idx) = pack_h2(rx, ry);
                }
            }
        }
    }
}

// QKV fused: blockIdx.z selects projection.
__global__ void __launch_bounds__(256) qkv_gemm(
    const __half* __restrict__ x,
    const __half* __restrict__ wq, const __half* __restrict__ wk,
    const __half* __restrict__ wv,
    const float* __restrict__ bq, const float* __restrict__ bk,
    const float* __restrict__ bv,
    __half* __restrict__ q, __half* __restrict__ k, __half* __restrict__ v)
{
    extern __shared__ char smem[];
    const int z = blockIdx.z;
    const __half* B = (z == 0) ? wq : (z == 1) ? wk : wv;
    const float* bias = (z == 0) ? bq : (z == 1) ? bk : bv;
    __half* o = (z == 0) ? q : (z == 1) ? k : v;
    const float scale = (z == 0) ? 0.125f : 1.0f;
    gemm_core<1>(smem, x, B, bias, nullptr, o, scale);
}

__global__ void __launch_bounds__(256) proj_gemm(
    const __half* __restrict__ y, const __half* __restrict__ wp,
    const float* __restrict__ bp, float* __restrict__ out)
{
    extern __shared__ char smem[];
    gemm_core<0>(smem, y, wp, bp, out, nullptr, 1.0f);
}

// ---------------------------------------------------------------------------
// Flash attention, fp16 mma.sync, fp32 softmax.
// CTA: 128 q-rows of one (b,h); 8 warps x 16 rows; kv tiles of 64.
// SMEM: Q 16K | stage{0,1}: K 8K, V 8K  => 48K total.
// ---------------------------------------------------------------------------
#define ATT_STG 16384
#define ATT_SMEM (16384 + 2 * ATT_STG)

__global__ void __launch_bounds__(256) attn_mma(
    const __half* __restrict__ q, const __half* __restrict__ k,
    const __half* __restrict__ v, __half* __restrict__ y)
{
    extern __shared__ char smem[];
    const uint32_t sb = smem_u32(smem);
    const int tid = threadIdx.x;
    const int wid = tid >> 5;
    const int lid = tid & 31;
    const int qt0 = blockIdx.x * 128;
    const int bh = blockIdx.y;
    const int wm = wid * 16;
    const size_t hb = (size_t)bh * TT * DD;

    const __half* kp = k + hb;
    const __half* vp = v + hb;

    // Q tile: 128 rows x 128B (64 halves) = 1024 16B units, 4 per thread
    #pragma unroll
    for (int it = 0; it < 4; ++it) {
        const int u = (it << 8) + tid;
        const int r = u >> 3, c = u & 7;
        CP_ASYNC16(sb + SWZ(r * 128 + c * 16),
                   q + hb + (size_t)(qt0 + r) * DD + c * 8);
    }
    CP_COMMIT();

    const int ntiles = 2 * blockIdx.x + 2;

    auto issue_kv = [&](int t, int stage) {
        const int kt0 = t * 64;
        #pragma unroll
        for (int it = 0; it < 4; ++it) {
            const int arr = it >> 1;              // 0=K, 1=V
            const int u = ((it & 1) << 8) + tid;  // 0..511
            const int r = u >> 3, c = u & 7;
            const __half* p = arr ? vp : kp;
            CP_ASYNC16(sb + 16384 + stage * ATT_STG + arr * 8192 + SWZ(r * 128 + c * 16),
                       p + (size_t)(kt0 + r) * DD + c * 8);
        }
        CP_COMMIT();
    };

    issue_kv(0, 0);
    CP_WAIT1();
    __syncthreads();

    // Q fragments held in registers for whole kernel
    uint32_t aq[4][4];
    {
        const int ar = wm + (lid & 15);
        const int ac = (lid >> 4) << 4;
        #pragma unroll
        for (int s = 0; s < 4; ++s) {
            const uint32_t off = SWZ(ar * 128 + s * 32 + ac);
            LDM_X4(aq[s][0], aq[s][1], aq[s][2], aq[s][3], sb + off);
        }
    }

    const int brow = (lid & 7) + ((lid >> 4) << 3);
    const int bcol = ((lid >> 3) & 1) << 4;
    const int vrow = (lid & 7) + (((lid >> 3) & 1) << 3);
    const int vcol = (lid >> 4) << 4;

    float oacc[8][4];
    #pragma unroll
    for (int j = 0; j < 8; ++j)
        #pragma unroll
        for (int e = 0; e < 4; ++e) oacc[j][e] = 0.f;
    float m0 = -1e30f, m1 = -1e30f, l0 = 0.f, l1 = 0.f;

    const int row0 = qt0 + wm + (lid >> 2);
    const int row1 = row0 + 8;
    const int colb = 2 * (lid & 3);

    for (int t = 0; t < ntiles; ++t) {
        if (t + 1 < ntiles) { issue_kv(t + 1, (t + 1) & 1); CP_WAIT1(); }
        else CP_WAIT0();
        __syncthreads();

        const int kt0 = t * 64;
        if (kt0 <= qt0 + wm + 15) {
            const uint32_t stg = sb + 16384 + (t & 1) * ATT_STG;
            const uint32_t kB = stg, vB = stg + 8192;

            // ---- S = Q K^T ----
            float sacc[8][4];
            #pragma unroll
            for (int j = 0; j < 8; ++j)
                #pragma unroll
                for (int e = 0; e < 4; ++e) sacc[j][e] = 0.f;

            #pragma unroll
            for (int s = 0; s < 4; ++s) {
                #pragma unroll
                for (int pr = 0; pr < 4; ++pr) {
                    const uint32_t boff = SWZ((pr * 16 + brow) * 128 + s * 32 + bcol);
                    uint32_t b0, b1, b2, b3;
                    LDM_X4(b0, b1, b2, b3, kB + boff);
                    MMA_F16(sacc[2 * pr + 0], aq[s], b0, b1);
                    MMA_F16(sacc[2 * pr + 1], aq[s], b2, b3);
                }
            }

            // ---- causal mask ----
            if (kt0 + 64 > qt0 + wm) {
                #pragma unroll
                for (int j = 0; j < 8; ++j) {
                    const int c0 = kt0 + j * 8 + colb;
                    if (c0 > row0)     sacc[j][0] = -1e30f;
                    if (c0 + 1 > row0) sacc[j][1] = -1e30f;
                    if (c0 > row1)     sacc[j][2] = -1e30f;
                    if (c0 + 1 > row1) sacc[j][3] = -1e30f;
                }
            }

            // ---- online softmax ----
            float mx0 = -1e30f, mx1 = -1e30f;
            #pragma unroll
            for (int j = 0; j < 8; ++j) {
                mx0 = fmaxf(mx0, fmaxf(sacc[j][0], sacc[j][1]));
                mx1 = fmaxf(mx1, fmaxf(sacc[j][2], sacc[j][3]));
            }
            mx0 = fmaxf(mx0, __shfl_xor_sync(0xffffffffu, mx0, 1));
            mx0 = fmaxf(mx0, __shfl_xor_sync(0xffffffffu, mx0, 2));
            mx1 = fmaxf(mx1, __shfl_xor_sync(0xffffffffu, mx1, 1));
            mx1 = fmaxf(mx1, __shfl_xor_sync(0xffffffffu, mx1, 2));
            const float mn0 = fmaxf(m0, mx0), mn1 = fmaxf(m1, mx1);
            const float al0 = __expf(m0 - mn0), al1 = __expf(m1 - mn1);
            m0 = mn0; m1 = mn1;

            float rs0 = 0.f, rs1 = 0.f;
            #pragma unroll
            for (int j = 0; j < 8; ++j) {
                sacc[j][0] = __expf(sacc[j][0] - m0);
                sacc[j][1] = __expf(sacc[j][1] - m0);
                sacc[j][2] = __expf(sacc[j][2] - m1);
                sacc[j][3] = __expf(sacc[j][3] - m1);
                rs0 += sacc[j][0] + sacc[j][1];
                rs1 += sacc[j][2] + sacc[j][3];
            }
            rs0 += __shfl_xor_sync(0xffffffffu, rs0, 1);
            rs0 += __shfl_xor_sync(0xffffffffu, rs0, 2);
            rs1 += __shfl_xor_sync(0xffffffffu, rs1, 1);
            rs1 += __shfl_xor_sync(0xffffffffu, rs1, 2);
            l0 = l0 * al0 + rs0;
            l1 = l1 * al1 + rs1;
            #pragma unroll
            for (int j = 0; j < 8; ++j) {
                oacc[j][0] *= al0; oacc[j][1] *= al0;
                oacc[j][2] *= al1; oacc[j][3] *= al1;
            }

            // ---- O += P V ----
            #pragma unroll
            for (int kk = 0; kk < 4; ++kk) {
                const int j0 = 2 * kk, j1 = j0 + 1;
                uint32_t ph[4];
                ph[0] = pack_h2(sacc[j0][0], sacc[j0][1]);
                ph[1] = pack_h2(sacc[j0][2], sacc[j0][3]);
                ph[2] = pack_h2(sacc[j1][0], sacc[j1][1]);
                ph[3] = pack_h2(sacc[j1][2], sacc[j1][3]);
                #pragma unroll
                for (int dd = 0; dd < 4; ++dd) {
                    const uint32_t voff = SWZ((kk * 16 + vrow) * 128 + dd * 32 + vcol);
                    uint32_t v0, v1, v2, v3;
                    LDM_X4T(v0, v1, v2, v3, vB + voff);
                    MMA_F16(oacc[2 * dd + 0], ph, v0, v1);
                    MMA_F16(oacc[2 * dd + 1], ph, v2, v3);
                }
            }
        }
        __syncthreads();
    }

    // ---- epilogue: normalize, write (b,t,c) fp16 ----
    const int b = bh >> 4, h = bh & 15;
    const float inv0 = 1.f / l0, inv1 = 1.f / l1;
    #pragma unroll
    for (int j = 0; j < 8; ++j) {
        const int d = j * 8 + colb;
        const size_t i0 = ((size_t)b * TT + row0) * CC + h * DD + d;
        const size_t i1 = ((size_t)b * TT + row1) * CC + h * DD + d;
        *(uint32_t*)(y + i0) = pack_h2(oacc[j][0] * inv0, oacc[j][1] * inv0);
        *(uint32_t*)(y + i1) = pack_h2(oacc[j][2] * inv1, oacc[j][3] * inv1);
    }
}

// ---------------------------------------------------------------------------
// Launch
// ---------------------------------------------------------------------------
extern "C" void kernel_launch(void* const* d_in, const int* in_sizes, int n_in,
                              void* d_out, int out_size)
{
    (void)in_sizes; (void)n_in; (void)out_size;
    const float* x  = (const float*)d_in[0];
    const float* Wk = (const float*)d_in[1];
    const float* bk = (const float*)d_in[2];
    const float* Wq = (const float*)d_in[3];
    const float* bq = (const float*)d_in[4];
    const float* Wv = (const float*)d_in[5];
    const float* bv = (const float*)d_in[6];
    const float* Wp = (const float*)d_in[7];
    const float* bp = (const float*)d_in[8];
    float* out = (float*)d_out;

    __half *px, *pq, *pk, *pv, *py, *pwq, *pwk, *pwv, *pwp;
    cudaGetSymbolAddress((void**)&px, g_x);
    cudaGetSymbolAddress((void**)&pq, g_q);
    cudaGetSymbolAddress((void**)&pk, g_k);
    cudaGetSymbolAddress((void**)&pv, g_v);
    cudaGetSymbolAddress((void**)&py, g_y);
    cudaGetSymbolAddress((void**)&pwq, g_wq);
    cudaGetSymbolAddress((void**)&pwk, g_wk);
    cudaGetSymbolAddress((void**)&pwv, g_wv);
    cudaGetSymbolAddress((void**)&pwp, g_wp);

    cvt_all<<<(XN4 + 4 * WN4 + 255) / 256, 256>>>(
        x, Wq, Wk, Wv, Wp, px, pwq, pwk, pwv, pwp);

    cudaFuncSetAttribute(qkv_gemm, cudaFuncAttributeMaxDynamicSharedMemorySize, GEMM_SMEM);
    cudaFuncSetAttribute(proj_gemm, cudaFuncAttributeMaxDynamicSharedMemorySize, GEMM_SMEM);
    cudaFuncSetAttribute(attn_mma, cudaFuncAttributeMaxDynamicSharedMemorySize, ATT_SMEM);

    qkv_gemm<<<dim3(CC / 128, MM / 128, 3), 256, GEMM_SMEM>>>(
        px, pwq, pwk, pwv, bq, bk, bv, pq, pk, pv);

    attn_mma<<<dim3(TT / 128, BB * HH), 256, ATT_SMEM>>>(pq, pk, pv, py);

    proj_gemm<<<dim3(CC / 128, MM / 128), 256, GEMM_SMEM>>>(py, pwp, bp, out);
}

// round 13
// speedup vs baseline: 3.6883x; 1.1610x over previous
#include <cuda_runtime.h>
#include <cuda_fp16.h>
#include <math.h>
#include <stdint.h>

// Problem constants
#define BB 4
#define TT 2048
#define CC 1024
#define HH 16
#define DD 64
#define MM (BB*TT)   // 8192 rows

// ---------------------------------------------------------------------------
// Scratch (__device__ globals; no allocation allowed) — all fp16
// ---------------------------------------------------------------------------
__device__ __half g_x[(size_t)MM * CC];
__device__ __half g_q[(size_t)MM * CC];   // (b,h,t,d), pre-scaled by 1/8
__device__ __half g_k[(size_t)MM * CC];
__device__ __half g_v[(size_t)MM * CC];
__device__ __half g_y[(size_t)MM * CC];   // (b,t,c)
__device__ __half g_wq[(size_t)CC * CC];
__device__ __half g_wk[(size_t)CC * CC];
__device__ __half g_wv[(size_t)CC * CC];
__device__ __half g_wp[(size_t)CC * CC];

// ---------------------------------------------------------------------------
// Helpers (baseline PTX only)
// ---------------------------------------------------------------------------
__device__ __forceinline__ uint32_t smem_u32(const void* p) {
    uint32_t a;
    asm("{ .reg .u64 t; cvta.to.shared.u64 t, %1; cvt.u32.u64 %0, t; }" : "=r"(a) : "l"(p));
    return a;
}
#define CP_ASYNC16(dst, src) \
    asm volatile("cp.async.cg.shared.global [%0], [%1], 16;" :: "r"(dst), "l"(src) : "memory")
#define CP_COMMIT() asm volatile("cp.async.commit_group;" ::: "memory")
#define CP_WAIT0()  asm volatile("cp.async.wait_group 0;" ::: "memory")
#define CP_WAIT1()  asm volatile("cp.async.wait_group 1;" ::: "memory")
#define CP_WAIT2()  asm volatile("cp.async.wait_group 2;" ::: "memory")

#define LDM_X4(r0, r1, r2, r3, a) \
    asm volatile("ldmatrix.sync.aligned.m8n8.x4.shared.b16 {%0,%1,%2,%3}, [%4];" \
        : "=r"(r0), "=r"(r1), "=r"(r2), "=r"(r3) : "r"(a))
#define LDM_X4T(r0, r1, r2, r3, a) \
    asm volatile("ldmatrix.sync.aligned.m8n8.x4.trans.shared.b16 {%0,%1,%2,%3}, [%4];" \
        : "=r"(r0), "=r"(r1), "=r"(r2), "=r"(r3) : "r"(a))

#define MMA_F16(acc, a, b0, b1) \
    asm volatile("mma.sync.aligned.m16n8k16.row.col.f32.f16.f16.f32 " \
        "{%0,%1,%2,%3},{%4,%5,%6,%7},{%8,%9},{%0,%1,%2,%3};" \
        : "+f"((acc)[0]), "+f"((acc)[1]), "+f"((acc)[2]), "+f"((acc)[3]) \
        : "r"((a)[0]), "r"((a)[1]), "r"((a)[2]), "r"((a)[3]), "r"(b0), "r"(b1))

#define SWZ(x) ((x) ^ (((x) >> 3) & 0x70))

__device__ __forceinline__ uint32_t pack_h2(float x, float y) {
    __half2 h = __floats2half2_rn(x, y);
    return *(uint32_t*)&h;
}

// ---------------------------------------------------------------------------
// Fused fp32 -> fp16 conversion for x + 4 weight matrices.
// ---------------------------------------------------------------------------
#define XN4 (MM * CC / 4)
#define WN4 (CC * CC / 4)

__global__ void __launch_bounds__(256) cvt_all(
    const float* __restrict__ x,
    const float* __restrict__ Wq, const float* __restrict__ Wk,
    const float* __restrict__ Wv, const float* __restrict__ Wp,
    __half* __restrict__ xo,
    __half* __restrict__ wqo, __half* __restrict__ wko,
    __half* __restrict__ wvo, __half* __restrict__ wpo)
{
    int i = blockIdx.x * blockDim.x + threadIdx.x;
    const float* src;
    __half* dst;
    int off;
    if (i < XN4) { src = x; dst = xo; off = i; }
    else {
        int j = i - XN4;
        const int w = j / WN4;
        off = j - w * WN4;
        if (w == 0)      { src = Wq; dst = wqo; }
        else if (w == 1) { src = Wk; dst = wko; }
        else if (w == 2) { src = Wv; dst = wvo; }
        else             { src = Wp; dst = wpo; }
    }
    float4 v = ((const float4*)src)[off];
    ((__half2*)dst)[2 * off + 0] = __floats2half2_rn(v.x, v.y);
    ((__half2*)dst)[2 * off + 1] = __floats2half2_rn(v.z, v.w);
}

// ---------------------------------------------------------------------------
// mma.sync fp16 GEMM: out(M,N) = (A(M,K) @ B(N,K)^T + bias) * scale
// CTA tile 128x64, 128 threads = 4 warps (2m x 2n), warp tile 64x32.
// K-chunk 64 halves (128B rows), 3-stage cp.async.
// Designed for 3 CTAs/SM: smem 24KB/stage * 3 = 72KB, natural regs.
// MODE 0: fp32 row-major out. MODE 1: fp16 head-split out.
// ---------------------------------------------------------------------------
#define KC 64
#define NCH (CC / KC)        // 16
#define STG_A 16384          // A: 128 rows * 128B
#define STG_B 8192           // B: 64 rows * 128B
#define STG_BYTES (STG_A + STG_B)   // 24576
#define GEMM_SMEM (3 * STG_BYTES)   // 73728

template<int MODE>
__device__ __forceinline__ void gemm_core(
    char* smem,
    const __half* __restrict__ A, const __half* __restrict__ B,
    const float* __restrict__ bias, float* __restrict__ outF,
    __half* __restrict__ outH, float scale)
{
    const uint32_t sbase = smem_u32(smem);
    const int tid = threadIdx.x;
    const int wid = tid >> 5;
    const int lid = tid & 31;
    const int m0 = blockIdx.y * 128;
    const int n0 = blockIdx.x * 64;
    const int wm = (wid & 1) * 64;
    const int wn = (wid >> 1) * 32;

    // ---- loader bases (compact: 1 smem offset + 2 global pointers) ----
    // per chunk: A = 1024 16B units (8 its), B = 512 (4 its); 128 threads.
    // it stride: 16 rows -> smem +2048 bytes (SWZ-additive), global +16*CC.
    const uint32_t ld_sw = SWZ(((tid >> 3) << 7) + ((tid & 7) << 4));
    const __half* srcA = A + (size_t)(m0 + (tid >> 3)) * CC + (tid & 7) * 8;
    const __half* srcB = B + (size_t)(n0 + (tid >> 3)) * CC + (tid & 7) * 8;

    // ---- ldmatrix offsets ----
    uint32_t a_off[4][4], b_off[2][4];
    #pragma unroll
    for (int mi = 0; mi < 4; ++mi)
        #pragma unroll
        for (int s = 0; s < 4; ++s) {
            const int r = wm + mi * 16 + (lid & 15);
            const int cb = s * 32 + ((lid >> 4) << 4);
            a_off[mi][s] = SWZ(r * 128 + cb);
        }
    #pragma unroll
    for (int pr = 0; pr < 2; ++pr)
        #pragma unroll
        for (int s = 0; s < 4; ++s) {
            const int r = wn + pr * 16 + (lid & 7) + ((lid >> 4) << 3);
            const int cb = s * 32 + (((lid >> 3) & 1) << 4);
            b_off[pr][s] = SWZ(r * 128 + cb);
        }

    float acc[4][4][4];
    #pragma unroll
    for (int i = 0; i < 4; ++i)
        #pragma unroll
        for (int j = 0; j < 4; ++j)
            #pragma unroll
            for (int e = 0; e < 4; ++e) acc[i][j][e] = 0.f;

    // ---- issue helper ----
    auto issue = [&](int ch, int stage) {
        const uint32_t so = sbase + stage * STG_BYTES + ld_sw;
        const __half* sa = srcA + ch * KC;
        const __half* sb2 = srcB + ch * KC;
        #pragma unroll
        for (int it = 0; it < 8; ++it)
            CP_ASYNC16(so + it * 2048, sa + it * 16 * CC);
        #pragma unroll
        for (int it = 0; it < 4; ++it)
            CP_ASYNC16(so + STG_A + it * 2048, sb2 + it * 16 * CC);
        CP_COMMIT();
    };

    issue(0, 0);
    issue(1, 1);

    for (int ch = 0; ch < NCH; ++ch) {
        const int nxt = ch + 2;
        if (nxt < NCH) issue(nxt, nxt % 3);
        else CP_COMMIT();
        CP_WAIT2();
        __syncthreads();

        const uint32_t Ab = sbase + (ch % 3) * STG_BYTES;
        const uint32_t Bb = Ab + STG_A;

        #pragma unroll
        for (int s = 0; s < 4; ++s) {
            uint32_t ah[4][4];
            #pragma unroll
            for (int mi = 0; mi < 4; ++mi)
                LDM_X4(ah[mi][0], ah[mi][1], ah[mi][2], ah[mi][3], Ab + a_off[mi][s]);
            #pragma unroll
            for (int pr = 0; pr < 2; ++pr) {
                uint32_t b0, b1, b2, b3;
                LDM_X4(b0, b1, b2, b3, Bb + b_off[pr][s]);
                #pragma unroll
                for (int mi = 0; mi < 4; ++mi) {
                    MMA_F16(acc[mi][2 * pr + 0], ah[mi], b0, b1);
                    MMA_F16(acc[mi][2 * pr + 1], ah[mi], b2, b3);
                }
            }
        }
        __syncthreads();
    }

    #pragma unroll
    for (int nj = 0; nj < 4; ++nj) {
        const int n = n0 + wn + nj * 8 + (lid & 3) * 2;
        const float bx = bias[n], by = bias[n + 1];
        #pragma unroll
        for (int mi = 0; mi < 4; ++mi) {
            #pragma unroll
            for (int half = 0; half < 2; ++half) {
                const int m = m0 + wm + mi * 16 + (lid >> 2) + half * 8;
                const float rx = (acc[mi][nj][2 * half + 0] + bx) * scale;
                const float ry = (acc[mi][nj][2 * half + 1] + by) * scale;
                if (MODE == 0) {
                    float2 r; r.x = rx; r.y = ry;
                    *(float2*)(outF + (size_t)m * CC + n) = r;
                } else {
                    const int b = m >> 11, t = m & (TT - 1);
                    const int h = n >> 6, d = n & 63;
                    const size_t idx = (((size_t)b * HH + h) * TT + t) * DD + d;
                    *(uint32_t*)(outH + idx) = pack_h2(rx, ry);
                }
            }
        }
    }
}

// QKV fused: blockIdx.z selects projection.
__global__ void __launch_bounds__(128) qkv_gemm(
    const __half* __restrict__ x,
    const __half* __restrict__ wq, const __half* __restrict__ wk,
    const __half* __restrict__ wv,
    const float* __restrict__ bq, const float* __restrict__ bk,
    const float* __restrict__ bv,
    __half* __restrict__ q, __half* __restrict__ k, __half* __restrict__ v)
{
    extern __shared__ char smem[];
    const int z = blockIdx.z;
    const __half* B = (z == 0) ? wq : (z == 1) ? wk : wv;
    const float* bias = (z == 0) ? bq : (z == 1) ? bk : bv;
    __half* o = (z == 0) ? q : (z == 1) ? k : v;
    const float scale = (z == 0) ? 0.125f : 1.0f;
    gemm_core<1>(smem, x, B, bias, nullptr, o, scale);
}

__global__ void __launch_bounds__(128) proj_gemm(
    const __half* __restrict__ y, const __half* __restrict__ wp,
    const float* __restrict__ bp, float* __restrict__ out)
{
    extern __shared__ char smem[];
    gemm_core<0>(smem, y, wp, bp, out, nullptr, 1.0f);
}

// ---------------------------------------------------------------------------
// Flash attention, fp16 mma.sync, fp32 softmax. (unchanged from round 11)
// CTA: 128 q-rows of one (b,h); 8 warps x 16 rows; kv tiles of 64.
// SMEM: Q 16K | stage{0,1}: K 8K, V 8K  => 48K total.
// ---------------------------------------------------------------------------
#define ATT_STG 16384
#define ATT_SMEM (16384 + 2 * ATT_STG)

__global__ void __launch_bounds__(256) attn_mma(
    const __half* __restrict__ q, const __half* __restrict__ k,
    const __half* __restrict__ v, __half* __restrict__ y)
{
    extern __shared__ char smem[];
    const uint32_t sb = smem_u32(smem);
    const int tid = threadIdx.x;
    const int wid = tid >> 5;
    const int lid = tid & 31;
    const int qt0 = blockIdx.x * 128;
    const int bh = blockIdx.y;
    const int wm = wid * 16;
    const size_t hb = (size_t)bh * TT * DD;

    const __half* kp = k + hb;
    const __half* vp = v + hb;

    #pragma unroll
    for (int it = 0; it < 4; ++it) {
        const int u = (it << 8) + tid;
        const int r = u >> 3, c = u & 7;
        CP_ASYNC16(sb + SWZ(r * 128 + c * 16),
                   q + hb + (size_t)(qt0 + r) * DD + c * 8);
    }
    CP_COMMIT();

    const int ntiles = 2 * blockIdx.x + 2;

    auto issue_kv = [&](int t, int stage) {
        const int kt0 = t * 64;
        #pragma unroll
        for (int it = 0; it < 4; ++it) {
            const int arr = it >> 1;
            const int u = ((it & 1) << 8) + tid;
            const int r = u >> 3, c = u & 7;
            const __half* p = arr ? vp : kp;
            CP_ASYNC16(sb + 16384 + stage * ATT_STG + arr * 8192 + SWZ(r * 128 + c * 16),
                       p + (size_t)(kt0 + r) * DD + c * 8);
        }
        CP_COMMIT();
    };

    issue_kv(0, 0);
    CP_WAIT1();
    __syncthreads();

    uint32_t aq[4][4];
    {
        const int ar = wm + (lid & 15);
        const int ac = (lid >> 4) << 4;
        #pragma unroll
        for (int s = 0; s < 4; ++s) {
            const uint32_t off = SWZ(ar * 128 + s * 32 + ac);
            LDM_X4(aq[s][0], aq[s][1], aq[s][2], aq[s][3], sb + off);
        }
    }

    const int brow = (lid & 7) + ((lid >> 4) << 3);
    const int bcol = ((lid >> 3) & 1) << 4;
    const int vrow = (lid & 7) + (((lid >> 3) & 1) << 3);
    const int vcol = (lid >> 4) << 4;

    float oacc[8][4];
    #pragma unroll
    for (int j = 0; j < 8; ++j)
        #pragma unroll
        for (int e = 0; e < 4; ++e) oacc[j][e] = 0.f;
    float m0 = -1e30f, m1 = -1e30f, l0 = 0.f, l1 = 0.f;

    const int row0 = qt0 + wm + (lid >> 2);
    const int row1 = row0 + 8;
    const int colb = 2 * (lid & 3);

    for (int t = 0; t < ntiles; ++t) {
        if (t + 1 < ntiles) { issue_kv(t + 1, (t + 1) & 1); CP_WAIT1(); }
        else CP_WAIT0();
        __syncthreads();

        const int kt0 = t * 64;
        if (kt0 <= qt0 + wm + 15) {
            const uint32_t stg = sb + 16384 + (t & 1) * ATT_STG;
            const uint32_t kB = stg, vB = stg + 8192;

            float sacc[8][4];
            #pragma unroll
            for (int j = 0; j < 8; ++j)
                #pragma unroll
                for (int e = 0; e < 4; ++e) sacc[j][e] = 0.f;

            #pragma unroll
            for (int s = 0; s < 4; ++s) {
                #pragma unroll
                for (int pr = 0; pr < 4; ++pr) {
                    const uint32_t boff = SWZ((pr * 16 + brow) * 128 + s * 32 + bcol);
                    uint32_t b0, b1, b2, b3;
                    LDM_X4(b0, b1, b2, b3, kB + boff);
                    MMA_F16(sacc[2 * pr + 0], aq[s], b0, b1);
                    MMA_F16(sacc[2 * pr + 1], aq[s], b2, b3);
                }
            }

            if (kt0 + 64 > qt0 + wm) {
                #pragma unroll
                for (int j = 0; j < 8; ++j) {
                    const int c0 = kt0 + j * 8 + colb;
                    if (c0 > row0)     sacc[j][0] = -1e30f;
                    if (c0 + 1 > row0) sacc[j][1] = -1e30f;
                    if (c0 > row1)     sacc[j][2] = -1e30f;
                    if (c0 + 1 > row1) sacc[j][3] = -1e30f;
                }
            }

            float mx0 = -1e30f, mx1 = -1e30f;
            #pragma unroll
            for (int j = 0; j < 8; ++j) {
                mx0 = fmaxf(mx0, fmaxf(sacc[j][0], sacc[j][1]));
                mx1 = fmaxf(mx1, fmaxf(sacc[j][2], sacc[j][3]));
            }
            mx0 = fmaxf(mx0, __shfl_xor_sync(0xffffffffu, mx0, 1));
            mx0 = fmaxf(mx0, __shfl_xor_sync(0xffffffffu, mx0, 2));
            mx1 = fmaxf(mx1, __shfl_xor_sync(0xffffffffu, mx1, 1));
            mx1 = fmaxf(mx1, __shfl_xor_sync(0xffffffffu, mx1, 2));
            const float mn0 = fmaxf(m0, mx0), mn1 = fmaxf(m1, mx1);
            const float al0 = __expf(m0 - mn0), al1 = __expf(m1 - mn1);
            m0 = mn0; m1 = mn1;

            float rs0 = 0.f, rs1 = 0.f;
            #pragma unroll
            for (int j = 0; j < 8; ++j) {
                sacc[j][0] = __expf(sacc[j][0] - m0);
                sacc[j][1] = __expf(sacc[j][1] - m0);
                sacc[j][2] = __expf(sacc[j][2] - m1);
                sacc[j][3] = __expf(sacc[j][3] - m1);
                rs0 += sacc[j][0] + sacc[j][1];
                rs1 += sacc[j][2] + sacc[j][3];
            }
            rs0 += __shfl_xor_sync(0xffffffffu, rs0, 1);
            rs0 += __shfl_xor_sync(0xffffffffu, rs0, 2);
            rs1 += __shfl_xor_sync(0xffffffffu, rs1, 1);
            rs1 += __shfl_xor_sync(0xffffffffu, rs1, 2);
            l0 = l0 * al0 + rs0;
            l1 = l1 * al1 + rs1;
            #pragma unroll
            for (int j = 0; j < 8; ++j) {
                oacc[j][0] *= al0; oacc[j][1] *= al0;
                oacc[j][2] *= al1; oacc[j][3] *= al1;
            }

            #pragma unroll
            for (int kk = 0; kk < 4; ++kk) {
                const int j0 = 2 * kk, j1 = j0 + 1;
                uint32_t ph[4];
                ph[0] = pack_h2(sacc[j0][0], sacc[j0][1]);
                ph[1] = pack_h2(sacc[j0][2], sacc[j0][3]);
                ph[2] = pack_h2(sacc[j1][0], sacc[j1][1]);
                ph[3] = pack_h2(sacc[j1][2], sacc[j1][3]);
                #pragma unroll
                for (int dd = 0; dd < 4; ++dd) {
                    const uint32_t voff = SWZ((kk * 16 + vrow) * 128 + dd * 32 + vcol);
                    uint32_t v0, v1, v2, v3;
                    LDM_X4T(v0, v1, v2, v3, vB + voff);
                    MMA_F16(oacc[2 * dd + 0], ph, v0, v1);
                    MMA_F16(oacc[2 * dd + 1], ph, v2, v3);
                }
            }
        }
        __syncthreads();
    }

    const int b = bh >> 4, h = bh & 15;
    const float inv0 = 1.f / l0, inv1 = 1.f / l1;
    #pragma unroll
    for (int j = 0; j < 8; ++j) {
        const int d = j * 8 + colb;
        const size_t i0 = ((size_t)b * TT + row0) * CC + h * DD + d;
        const size_t i1 = ((size_t)b * TT + row1) * CC + h * DD + d;
        *(uint32_t*)(y + i0) = pack_h2(oacc[j][0] * inv0, oacc[j][1] * inv0);
        *(uint32_t*)(y + i1) = pack_h2(oacc[j][2] * inv1, oacc[j][3] * inv1);
    }
}

// ---------------------------------------------------------------------------
// Launch
// ---------------------------------------------------------------------------
extern "C" void kernel_launch(void* const* d_in, const int* in_sizes, int n_in,
                              void* d_out, int out_size)
{
    (void)in_sizes; (void)n_in; (void)out_size;
    const float* x  = (const float*)d_in[0];
    const float* Wk = (const float*)d_in[1];
    const float* bk = (const float*)d_in[2];
    const float* Wq = (const float*)d_in[3];
    const float* bq = (const float*)d_in[4];
    const float* Wv = (const float*)d_in[5];
    const float* bv = (const float*)d_in[6];
    const float* Wp = (const float*)d_in[7];
    const float* bp = (const float*)d_in[8];
    float* out = (float*)d_out;

    __half *px, *pq, *pk, *pv, *py, *pwq, *pwk, *pwv, *pwp;
    cudaGetSymbolAddress((void**)&px, g_x);
    cudaGetSymbolAddress((void**)&pq, g_q);
    cudaGetSymbolAddress((void**)&pk, g_k);
    cudaGetSymbolAddress((void**)&pv, g_v);
    cudaGetSymbolAddress((void**)&py, g_y);
    cudaGetSymbolAddress((void**)&pwq, g_wq);
    cudaGetSymbolAddress((void**)&pwk, g_wk);
    cudaGetSymbolAddress((void**)&pwv, g_wv);
    cudaGetSymbolAddress((void**)&pwp, g_wp);

    cvt_all<<<(XN4 + 4 * WN4 + 255) / 256, 256>>>(
        x, Wq, Wk, Wv, Wp, px, pwq, pwk, pwv, pwp);

    cudaFuncSetAttribute(qkv_gemm, cudaFuncAttributeMaxDynamicSharedMemorySize, GEMM_SMEM);
    cudaFuncSetAttribute(proj_gemm, cudaFuncAttributeMaxDynamicSharedMemorySize, GEMM_SMEM);
    cudaFuncSetAttribute(attn_mma, cudaFuncAttributeMaxDynamicSharedMemorySize, ATT_SMEM);

    qkv_gemm<<<dim3(CC / 64, MM / 128, 3), 128, GEMM_SMEM>>>(
        px, pwq, pwk, pwv, bq, bk, bv, pq, pk, pv);

    attn_mma<<<dim3(TT / 128, BB * HH), 256, ATT_SMEM>>>(pq, pk, pv, py);

    proj_gemm<<<dim3(CC / 64, MM / 128), 128, GEMM_SMEM>>>(py, pwp, bp, out);
}

// round 15
// speedup vs baseline: 3.7528x; 1.0175x over previous
#include <cuda_runtime.h>
#include <cuda_fp16.h>
#include <math.h>
#include <stdint.h>

// Problem constants
#define BB 4
#define TT 2048
#define CC 1024
#define HH 16
#define DD 64
#define MM (BB*TT)   // 8192 rows

// ---------------------------------------------------------------------------
// Scratch (__device__ globals; no allocation allowed) — all fp16
// ---------------------------------------------------------------------------
__device__ __half g_x[(size_t)MM * CC];
__device__ __half g_q[(size_t)MM * CC];   // (b,h,t,d), pre-scaled by 1/8
__device__ __half g_k[(size_t)MM * CC];
__device__ __half g_v[(size_t)MM * CC];
__device__ __half g_y[(size_t)MM * CC];   // (b,t,c)
__device__ __half g_wq[(size_t)CC * CC];
__device__ __half g_wk[(size_t)CC * CC];
__device__ __half g_wv[(size_t)CC * CC];
__device__ __half g_wp[(size_t)CC * CC];

// ---------------------------------------------------------------------------
// Helpers (baseline PTX only)
// ---------------------------------------------------------------------------
__device__ __forceinline__ uint32_t smem_u32(const void* p) {
    uint32_t a;
    asm("{ .reg .u64 t; cvta.to.shared.u64 t, %1; cvt.u32.u64 %0, t; }" : "=r"(a) : "l"(p));
    return a;
}
#define CP_ASYNC16(dst, src) \
    asm volatile("cp.async.cg.shared.global [%0], [%1], 16;" :: "r"(dst), "l"(src) : "memory")
#define CP_COMMIT() asm volatile("cp.async.commit_group;" ::: "memory")
#define CP_WAIT0()  asm volatile("cp.async.wait_group 0;" ::: "memory")
#define CP_WAIT1()  asm volatile("cp.async.wait_group 1;" ::: "memory")

#define LDM_X4(r0, r1, r2, r3, a) \
    asm volatile("ldmatrix.sync.aligned.m8n8.x4.shared.b16 {%0,%1,%2,%3}, [%4];" \
        : "=r"(r0), "=r"(r1), "=r"(r2), "=r"(r3) : "r"(a))
#define LDM_X4T(r0, r1, r2, r3, a) \
    asm volatile("ldmatrix.sync.aligned.m8n8.x4.trans.shared.b16 {%0,%1,%2,%3}, [%4];" \
        : "=r"(r0), "=r"(r1), "=r"(r2), "=r"(r3) : "r"(a))

#define MMA_F16(acc, a, b0, b1) \
    asm volatile("mma.sync.aligned.m16n8k16.row.col.f32.f16.f16.f32 " \
        "{%0,%1,%2,%3},{%4,%5,%6,%7},{%8,%9},{%0,%1,%2,%3};" \
        : "+f"((acc)[0]), "+f"((acc)[1]), "+f"((acc)[2]), "+f"((acc)[3]) \
        : "r"((a)[0]), "r"((a)[1]), "r"((a)[2]), "r"((a)[3]), "r"(b0), "r"(b1))

#define SWZ(x) ((x) ^ (((x) >> 3) & 0x70))

__device__ __forceinline__ uint32_t pack_h2(float x, float y) {
    __half2 h = __floats2half2_rn(x, y);
    return *(uint32_t*)&h;
}

// ---------------------------------------------------------------------------
// Fused fp32 -> fp16 conversion for x + 4 weight matrices.
// ---------------------------------------------------------------------------
#define XN4 (MM * CC / 4)
#define WN4 (CC * CC / 4)

__global__ void __launch_bounds__(256) cvt_all(
    const float* __restrict__ x,
    const float* __restrict__ Wq, const float* __restrict__ Wk,
    const float* __restrict__ Wv, const float* __restrict__ Wp,
    __half* __restrict__ xo,
    __half* __restrict__ wqo, __half* __restrict__ wko,
    __half* __restrict__ wvo, __half* __restrict__ wpo)
{
    int i = blockIdx.x * blockDim.x + threadIdx.x;
    const float* src;
    __half* dst;
    int off;
    if (i < XN4) { src = x; dst = xo; off = i; }
    else {
        int j = i - XN4;
        const int w = j / WN4;
        off = j - w * WN4;
        if (w == 0)      { src = Wq; dst = wqo; }
        else if (w == 1) { src = Wk; dst = wko; }
        else if (w == 2) { src = Wv; dst = wvo; }
        else             { src = Wp; dst = wpo; }
    }
    float4 v = ((const float4*)src)[off];
    ((__half2*)dst)[2 * off + 0] = __floats2half2_rn(v.x, v.y);
    ((__half2*)dst)[2 * off + 1] = __floats2half2_rn(v.z, v.w);
}

// ---------------------------------------------------------------------------
// mma.sync fp16 GEMM: out(M,N) = (A(M,K) @ B(N,K)^T + bias) * scale
// CTA tile 128x64, 128 threads = 4 warps (2m x 2n), warp tile 64x32.
// K-chunk 64 halves (128B rows), 2-stage cp.async (issue-1-ahead) so
// smem = 48KB -> 4 CTAs/SM = 16 warps/SM; regs capped at 128 (fits at 126).
// MODE 0: fp32 row-major out. MODE 1: fp16 head-split out.
// ---------------------------------------------------------------------------
#define KC 64
#define NCH (CC / KC)        // 16
#define STG_A 16384          // A: 128 rows * 128B
#define STG_B 8192           // B: 64 rows * 128B
#define STG_BYTES (STG_A + STG_B)   // 24576
#define GEMM_SMEM (2 * STG_BYTES)   // 49152

template<int MODE>
__device__ __forceinline__ void gemm_core(
    char* smem,
    const __half* __restrict__ A, const __half* __restrict__ B,
    const float* __restrict__ bias, float* __restrict__ outF,
    __half* __restrict__ outH, float scale)
{
    const uint32_t sbase = smem_u32(smem);
    const int tid = threadIdx.x;
    const int wid = tid >> 5;
    const int lid = tid & 31;
    const int m0 = blockIdx.y * 128;
    const int n0 = blockIdx.x * 64;
    const int wm = (wid & 1) * 64;
    const int wn = (wid >> 1) * 32;

    // ---- loader bases ----
    const uint32_t ld_sw = SWZ(((tid >> 3) << 7) + ((tid & 7) << 4));
    const __half* srcA = A + (size_t)(m0 + (tid >> 3)) * CC + (tid & 7) * 8;
    const __half* srcB = B + (size_t)(n0 + (tid >> 3)) * CC + (tid & 7) * 8;

    // ---- ldmatrix offsets ----
    uint32_t a_off[4][4], b_off[2][4];
    #pragma unroll
    for (int mi = 0; mi < 4; ++mi)
        #pragma unroll
        for (int s = 0; s < 4; ++s) {
            const int r = wm + mi * 16 + (lid & 15);
            const int cb = s * 32 + ((lid >> 4) << 4);
            a_off[mi][s] = SWZ(r * 128 + cb);
        }
    #pragma unroll
    for (int pr = 0; pr < 2; ++pr)
        #pragma unroll
        for (int s = 0; s < 4; ++s) {
            const int r = wn + pr * 16 + (lid & 7) + ((lid >> 4) << 3);
            const int cb = s * 32 + (((lid >> 3) & 1) << 4);
            b_off[pr][s] = SWZ(r * 128 + cb);
        }

    float acc[4][4][4];
    #pragma unroll
    for (int i = 0; i < 4; ++i)
        #pragma unroll
        for (int j = 0; j < 4; ++j)
            #pragma unroll
            for (int e = 0; e < 4; ++e) acc[i][j][e] = 0.f;

    // ---- issue helper (one K-chunk into one stage) ----
    auto issue = [&](int ch, int stage) {
        const uint32_t so = sbase + stage * STG_BYTES + ld_sw;
        const __half* sa = srcA + ch * KC;
        const __half* sb2 = srcB + ch * KC;
        #pragma unroll
        for (int it = 0; it < 8; ++it)
            CP_ASYNC16(so + it * 2048, sa + it * 16 * CC);
        #pragma unroll
        for (int it = 0; it < 4; ++it)
            CP_ASYNC16(so + STG_A + it * 2048, sb2 + it * 16 * CC);
        CP_COMMIT();
    };

    issue(0, 0);

    for (int ch = 0; ch < NCH; ++ch) {
        if (ch + 1 < NCH) {
            issue(ch + 1, (ch + 1) & 1);
            CP_WAIT1();            // chunk ch landed; ch+1 still in flight
        } else {
            CP_WAIT0();
        }
        __syncthreads();

        const uint32_t Ab = sbase + (ch & 1) * STG_BYTES;
        const uint32_t Bb = Ab + STG_A;

        #pragma unroll
        for (int s = 0; s < 4; ++s) {
            uint32_t ah[4][4];
            #pragma unroll
            for (int mi = 0; mi < 4; ++mi)
                LDM_X4(ah[mi][0], ah[mi][1], ah[mi][2], ah[mi][3], Ab + a_off[mi][s]);
            #pragma unroll
            for (int pr = 0; pr < 2; ++pr) {
                uint32_t b0, b1, b2, b3;
                LDM_X4(b0, b1, b2, b3, Bb + b_off[pr][s]);
                #pragma unroll
                for (int mi = 0; mi < 4; ++mi) {
                    MMA_F16(acc[mi][2 * pr + 0], ah[mi], b0, b1);
                    MMA_F16(acc[mi][2 * pr + 1], ah[mi], b2, b3);
                }
            }
        }
        __syncthreads();   // all reads of this stage done before re-issue
    }

    #pragma unroll
    for (int nj = 0; nj < 4; ++nj) {
        const int n = n0 + wn + nj * 8 + (lid & 3) * 2;
        const float bx = bias[n], by = bias[n + 1];
        #pragma unroll
        for (int mi = 0; mi < 4; ++mi) {
            #pragma unroll
            for (int half = 0; half < 2; ++half) {
                const int m = m0 + wm + mi * 16 + (lid >> 2) + half * 8;
                const float rx = (acc[mi][nj][2 * half + 0] + bx) * scale;
                const float ry = (acc[mi][nj][2 * half + 1] + by) * scale;
                if (MODE == 0) {
                    float2 r; r.x = rx; r.y = ry;
                    *(float2*)(outF + (size_t)m * CC + n) = r;
                } else {
                    const int b = m >> 11, t = m & (TT - 1);
                    const int h = n >> 6, d = n & 63;
                    const size_t idx = (((size_t)b * HH + h) * TT + t) * DD + d;
                    *(uint32_t*)(outH + idx) = pack_h2(rx, ry);
                }
            }
        }
    }
}

// QKV fused: blockIdx.z selects projection.
__global__ void __launch_bounds__(128, 4) qkv_gemm(
    const __half* __restrict__ x,
    const __half* __restrict__ wq, const __half* __restrict__ wk,
    const __half* __restrict__ wv,
    const float* __restrict__ bq, const float* __restrict__ bk,
    const float* __restrict__ bv,
    __half* __restrict__ q, __half* __restrict__ k, __half* __restrict__ v)
{
    extern __shared__ char smem[];
    const int z = blockIdx.z;
    const __half* B = (z == 0) ? wq : (z == 1) ? wk : wv;
    const float* bias = (z == 0) ? bq : (z == 1) ? bk : bv;
    __half* o = (z == 0) ? q : (z == 1) ? k : v;
    const float scale = (z == 0) ? 0.125f : 1.0f;
    gemm_core<1>(smem, x, B, bias, nullptr, o, scale);
}

__global__ void __launch_bounds__(128, 4) proj_gemm(
    const __half* __restrict__ y, const __half* __restrict__ wp,
    const float* __restrict__ bp, float* __restrict__ out)
{
    extern __shared__ char smem[];
    gemm_core<0>(smem, y, wp, bp, out, nullptr, 1.0f);
}

// ---------------------------------------------------------------------------
// Flash attention, fp16 mma.sync, fp32 softmax. (unchanged)
// CTA: 128 q-rows of one (b,h); 8 warps x 16 rows; kv tiles of 64.
// SMEM: Q 16K | stage{0,1}: K 8K, V 8K  => 48K total.
// ---------------------------------------------------------------------------
#define ATT_STG 16384
#define ATT_SMEM (16384 + 2 * ATT_STG)

__global__ void __launch_bounds__(256) attn_mma(
    const __half* __restrict__ q, const __half* __restrict__ k,
    const __half* __restrict__ v, __half* __restrict__ y)
{
    extern __shared__ char smem[];
    const uint32_t sb = smem_u32(smem);
    const int tid = threadIdx.x;
    const int wid = tid >> 5;
    const int lid = tid & 31;
    const int qt0 = blockIdx.x * 128;
    const int bh = blockIdx.y;
    const int wm = wid * 16;
    const size_t hb = (size_t)bh * TT * DD;

    const __half* kp = k + hb;
    const __half* vp = v + hb;

    #pragma unroll
    for (int it = 0; it < 4; ++it) {
        const int u = (it << 8) + tid;
        const int r = u >> 3, c = u & 7;
        CP_ASYNC16(sb + SWZ(r * 128 + c * 16),
                   q + hb + (size_t)(qt0 + r) * DD + c * 8);
    }
    CP_COMMIT();

    const int ntiles = 2 * blockIdx.x + 2;

    auto issue_kv = [&](int t, int stage) {
        const int kt0 = t * 64;
        #pragma unroll
        for (int it = 0; it < 4; ++it) {
            const int arr = it >> 1;
            const int u = ((it & 1) << 8) + tid;
            const int r = u >> 3, c = u & 7;
            const __half* p = arr ? vp : kp;
            CP_ASYNC16(sb + 16384 + stage * ATT_STG + arr * 8192 + SWZ(r * 128 + c * 16),
                       p + (size_t)(kt0 + r) * DD + c * 8);
        }
        CP_COMMIT();
    };

    issue_kv(0, 0);
    CP_WAIT1();
    __syncthreads();

    uint32_t aq[4][4];
    {
        const int ar = wm + (lid & 15);
        const int ac = (lid >> 4) << 4;
        #pragma unroll
        for (int s = 0; s < 4; ++s) {
            const uint32_t off = SWZ(ar * 128 + s * 32 + ac);
            LDM_X4(aq[s][0], aq[s][1], aq[s][2], aq[s][3], sb + off);
        }
    }

    const int brow = (lid & 7) + ((lid >> 4) << 3);
    const int bcol = ((lid >> 3) & 1) << 4;
    const int vrow = (lid & 7) + (((lid >> 3) & 1) << 3);
    const int vcol = (lid >> 4) << 4;

    float oacc[8][4];
    #pragma unroll
    for (int j = 0; j < 8; ++j)
        #pragma unroll
        for (int e = 0; e < 4; ++e) oacc[j][e] = 0.f;
    float m0 = -1e30f, m1 = -1e30f, l0 = 0.f, l1 = 0.f;

    const int row0 = qt0 + wm + (lid >> 2);
    const int row1 = row0 + 8;
    const int colb = 2 * (lid & 3);

    for (int t = 0; t < ntiles; ++t) {
        if (t + 1 < ntiles) { issue_kv(t + 1, (t + 1) & 1); CP_WAIT1(); }
        else CP_WAIT0();
        __syncthreads();

        const int kt0 = t * 64;
        if (kt0 <= qt0 + wm + 15) {
            const uint32_t stg = sb + 16384 + (t & 1) * ATT_STG;
            const uint32_t kB = stg, vB = stg + 8192;

            float sacc[8][4];
            #pragma unroll
            for (int j = 0; j < 8; ++j)
                #pragma unroll
                for (int e = 0; e < 4; ++e) sacc[j][e] = 0.f;

            #pragma unroll
            for (int s = 0; s < 4; ++s) {
                #pragma unroll
                for (int pr = 0; pr < 4; ++pr) {
                    const uint32_t boff = SWZ((pr * 16 + brow) * 128 + s * 32 + bcol);
                    uint32_t b0, b1, b2, b3;
                    LDM_X4(b0, b1, b2, b3, kB + boff);
                    MMA_F16(sacc[2 * pr + 0], aq[s], b0, b1);
                    MMA_F16(sacc[2 * pr + 1], aq[s], b2, b3);
                }
            }

            if (kt0 + 64 > qt0 + wm) {
                #pragma unroll
                for (int j = 0; j < 8; ++j) {
                    const int c0 = kt0 + j * 8 + colb;
                    if (c0 > row0)     sacc[j][0] = -1e30f;
                    if (c0 + 1 > row0) sacc[j][1] = -1e30f;
                    if (c0 > row1)     sacc[j][2] = -1e30f;
                    if (c0 + 1 > row1) sacc[j][3] = -1e30f;
                }
            }

            float mx0 = -1e30f, mx1 = -1e30f;
            #pragma unroll
            for (int j = 0; j < 8; ++j) {
                mx0 = fmaxf(mx0, fmaxf(sacc[j][0], sacc[j][1]));
                mx1 = fmaxf(mx1, fmaxf(sacc[j][2], sacc[j][3]));
            }
            mx0 = fmaxf(mx0, __shfl_xor_sync(0xffffffffu, mx0, 1));
            mx0 = fmaxf(mx0, __shfl_xor_sync(0xffffffffu, mx0, 2));
            mx1 = fmaxf(mx1, __shfl_xor_sync(0xffffffffu, mx1, 1));
            mx1 = fmaxf(mx1, __shfl_xor_sync(0xffffffffu, mx1, 2));
            const float mn0 = fmaxf(m0, mx0), mn1 = fmaxf(m1, mx1);
            const float al0 = __expf(m0 - mn0), al1 = __expf(m1 - mn1);
            m0 = mn0; m1 = mn1;

            float rs0 = 0.f, rs1 = 0.f;
            #pragma unroll
            for (int j = 0; j < 8; ++j) {
                sacc[j][0] = __expf(sacc[j][0] - m0);
                sacc[j][1] = __expf(sacc[j][1] - m0);
                sacc[j][2] = __expf(sacc[j][2] - m1);
                sacc[j][3] = __expf(sacc[j][3] - m1);
                rs0 += sacc[j][0] + sacc[j][1];
                rs1 += sacc[j][2] + sacc[j][3];
            }
            rs0 += __shfl_xor_sync(0xffffffffu, rs0, 1);
            rs0 += __shfl_xor_sync(0xffffffffu, rs0, 2);
            rs1 += __shfl_xor_sync(0xffffffffu, rs1, 1);
            rs1 += __shfl_xor_sync(0xffffffffu, rs1, 2);
            l0 = l0 * al0 + rs0;
            l1 = l1 * al1 + rs1;
            #pragma unroll
            for (int j = 0; j < 8; ++j) {
                oacc[j][0] *= al0; oacc[j][1] *= al0;
                oacc[j][2] *= al1; oacc[j][3] *= al1;
            }

            #pragma unroll
            for (int kk = 0; kk < 4; ++kk) {
                const int j0 = 2 * kk, j1 = j0 + 1;
                uint32_t ph[4];
                ph[0] = pack_h2(sacc[j0][0], sacc[j0][1]);
                ph[1] = pack_h2(sacc[j0][2], sacc[j0][3]);
                ph[2] = pack_h2(sacc[j1][0], sacc[j1][1]);
                ph[3] = pack_h2(sacc[j1][2], sacc[j1][3]);
                #pragma unroll
                for (int dd = 0; dd < 4; ++dd) {
                    const uint32_t voff = SWZ((kk * 16 + vrow) * 128 + dd * 32 + vcol);
                    uint32_t v0, v1, v2, v3;
                    LDM_X4T(v0, v1, v2, v3, vB + voff);
                    MMA_F16(oacc[2 * dd + 0], ph, v0, v1);
                    MMA_F16(oacc[2 * dd + 1], ph, v2, v3);
                }
            }
        }
        __syncthreads();
    }

    const int b = bh >> 4, h = bh & 15;
    const float inv0 = 1.f / l0, inv1 = 1.f / l1;
    #pragma unroll
    for (int j = 0; j < 8; ++j) {
        const int d = j * 8 + colb;
        const size_t i0 = ((size_t)b * TT + row0) * CC + h * DD + d;
        const size_t i1 = ((size_t)b * TT + row1) * CC + h * DD + d;
        *(uint32_t*)(y + i0) = pack_h2(oacc[j][0] * inv0, oacc[j][1] * inv0);
        *(uint32_t*)(y + i1) = pack_h2(oacc[j][2] * inv1, oacc[j][3] * inv1);
    }
}

// ---------------------------------------------------------------------------
// Launch
// ---------------------------------------------------------------------------
extern "C" void kernel_launch(void* const* d_in, const int* in_sizes, int n_in,
                              void* d_out, int out_size)
{
    (void)in_sizes; (void)n_in; (void)out_size;
    const float* x  = (const float*)d_in[0];
    const float* Wk = (const float*)d_in[1];
    const float* bk = (const float*)d_in[2];
    const float* Wq = (const float*)d_in[3];
    const float* bq = (const float*)d_in[4];
    const float* Wv = (const float*)d_in[5];
    const float* bv = (const float*)d_in[6];
    const float* Wp = (const float*)d_in[7];
    const float* bp = (const float*)d_in[8];
    float* out = (float*)d_out;

    __half *px, *pq, *pk, *pv, *py, *pwq, *pwk, *pwv, *pwp;
    cudaGetSymbolAddress((void**)&px, g_x);
    cudaGetSymbolAddress((void**)&pq, g_q);
    cudaGetSymbolAddress((void**)&pk, g_k);
    cudaGetSymbolAddress((void**)&pv, g_v);
    cudaGetSymbolAddress((void**)&py, g_y);
    cudaGetSymbolAddress((void**)&pwq, g_wq);
    cudaGetSymbolAddress((void**)&pwk, g_wk);
    cudaGetSymbolAddress((void**)&pwv, g_wv);
    cudaGetSymbolAddress((void**)&pwp, g_wp);

    cvt_all<<<(XN4 + 4 * WN4 + 255) / 256, 256>>>(
        x, Wq, Wk, Wv, Wp, px, pwq, pwk, pwv, pwp);

    cudaFuncSetAttribute(qkv_gemm, cudaFuncAttributeMaxDynamicSharedMemorySize, GEMM_SMEM);
    cudaFuncSetAttribute(proj_gemm, cudaFuncAttributeMaxDynamicSharedMemorySize, GEMM_SMEM);
    cudaFuncSetAttribute(attn_mma, cudaFuncAttributeMaxDynamicSharedMemorySize, ATT_SMEM);

    qkv_gemm<<<dim3(CC / 64, MM / 128, 3), 128, GEMM_SMEM>>>(
        px, pwq, pwk, pwv, bq, bk, bv, pq, pk, pv);

    attn_mma<<<dim3(TT / 128, BB * HH), 256, ATT_SMEM>>>(pq, pk, pv, py);

    proj_gemm<<<dim3(CC / 64, MM / 128), 128, GEMM_SMEM>>>(py, pwp, bp, out);
}

// round 16
// speedup vs baseline: 4.4932x; 1.1973x over previous
#include <cuda_runtime.h>
#include <cuda_fp16.h>
#include <math.h>
#include <stdint.h>

// Problem constants
#define BB 4
#define TT 2048
#define CC 1024
#define HH 16
#define DD 64
#define MM (BB*TT)   // 8192 rows

// ---------------------------------------------------------------------------
// Scratch (__device__ globals; no allocation allowed) — all fp16
// ---------------------------------------------------------------------------
__device__ __half g_x[(size_t)MM * CC];
__device__ __half g_q[(size_t)MM * CC];   // (b,h,t,d), pre-scaled by log2e/8
__device__ __half g_k[(size_t)MM * CC];
__device__ __half g_v[(size_t)MM * CC];
__device__ __half g_y[(size_t)MM * CC];   // (b,t,c)
__device__ __half g_wq[(size_t)CC * CC];
__device__ __half g_wk[(size_t)CC * CC];
__device__ __half g_wv[(size_t)CC * CC];
__device__ __half g_wp[(size_t)CC * CC];

// ---------------------------------------------------------------------------
// Helpers (baseline PTX only)
// ---------------------------------------------------------------------------
__device__ __forceinline__ uint32_t smem_u32(const void* p) {
    uint32_t a;
    asm("{ .reg .u64 t; cvta.to.shared.u64 t, %1; cvt.u32.u64 %0, t; }" : "=r"(a) : "l"(p));
    return a;
}
#define CP_ASYNC16(dst, src) \
    asm volatile("cp.async.cg.shared.global [%0], [%1], 16;" :: "r"(dst), "l"(src) : "memory")
#define CP_COMMIT() asm volatile("cp.async.commit_group;" ::: "memory")
#define CP_WAIT0()  asm volatile("cp.async.wait_group 0;" ::: "memory")
#define CP_WAIT1()  asm volatile("cp.async.wait_group 1;" ::: "memory")

#define LDM_X4(r0, r1, r2, r3, a) \
    asm volatile("ldmatrix.sync.aligned.m8n8.x4.shared.b16 {%0,%1,%2,%3}, [%4];" \
        : "=r"(r0), "=r"(r1), "=r"(r2), "=r"(r3) : "r"(a))
#define LDM_X4T(r0, r1, r2, r3, a) \
    asm volatile("ldmatrix.sync.aligned.m8n8.x4.trans.shared.b16 {%0,%1,%2,%3}, [%4];" \
        : "=r"(r0), "=r"(r1), "=r"(r2), "=r"(r3) : "r"(a))

#define MMA_F16(acc, a, b0, b1) \
    asm volatile("mma.sync.aligned.m16n8k16.row.col.f32.f16.f16.f32 " \
        "{%0,%1,%2,%3},{%4,%5,%6,%7},{%8,%9},{%0,%1,%2,%3};" \
        : "+f"((acc)[0]), "+f"((acc)[1]), "+f"((acc)[2]), "+f"((acc)[3]) \
        : "r"((a)[0]), "r"((a)[1]), "r"((a)[2]), "r"((a)[3]), "r"(b0), "r"(b1))

#define SWZ(x) ((x) ^ (((x) >> 3) & 0x70))

__device__ __forceinline__ uint32_t pack_h2(float x, float y) {
    __half2 h = __floats2half2_rn(x, y);
    return *(uint32_t*)&h;
}
__device__ __forceinline__ float ex2f(float x) {
    float r;
    asm("ex2.approx.f32 %0, %1;" : "=f"(r) : "f"(x));
    return r;
}

// ---------------------------------------------------------------------------
// Fused fp32 -> fp16 conversion for x + 4 weight matrices.
// ---------------------------------------------------------------------------
#define XN4 (MM * CC / 4)
#define WN4 (CC * CC / 4)

__global__ void __launch_bounds__(256) cvt_all(
    const float* __restrict__ x,
    const float* __restrict__ Wq, const float* __restrict__ Wk,
    const float* __restrict__ Wv, const float* __restrict__ Wp,
    __half* __restrict__ xo,
    __half* __restrict__ wqo, __half* __restrict__ wko,
    __half* __restrict__ wvo, __half* __restrict__ wpo)
{
    int i = blockIdx.x * blockDim.x + threadIdx.x;
    const float* src;
    __half* dst;
    int off;
    if (i < XN4) { src = x; dst = xo; off = i; }
    else {
        int j = i - XN4;
        const int w = j / WN4;
        off = j - w * WN4;
        if (w == 0)      { src = Wq; dst = wqo; }
        else if (w == 1) { src = Wk; dst = wko; }
        else if (w == 2) { src = Wv; dst = wvo; }
        else             { src = Wp; dst = wpo; }
    }
    float4 v = ((const float4*)src)[off];
    ((__half2*)dst)[2 * off + 0] = __floats2half2_rn(v.x, v.y);
    ((__half2*)dst)[2 * off + 1] = __floats2half2_rn(v.z, v.w);
}

// ---------------------------------------------------------------------------
// mma.sync fp16 GEMM (unchanged from round 15 — 63.3% tensor, protect it).
// CTA tile 128x64, 128 threads = 4 warps (2m x 2n), warp tile 64x32.
// K-chunk 64, 2-stage cp.async, 4 CTAs/SM.
// ---------------------------------------------------------------------------
#define KC 64
#define NCH (CC / KC)        // 16
#define STG_A 16384
#define STG_B 8192
#define STG_BYTES (STG_A + STG_B)   // 24576
#define GEMM_SMEM (2 * STG_BYTES)   // 49152

template<int MODE>
__device__ __forceinline__ void gemm_core(
    char* smem,
    const __half* __restrict__ A, const __half* __restrict__ B,
    const float* __restrict__ bias, float* __restrict__ outF,
    __half* __restrict__ outH, float scale)
{
    const uint32_t sbase = smem_u32(smem);
    const int tid = threadIdx.x;
    const int wid = tid >> 5;
    const int lid = tid & 31;
    const int m0 = blockIdx.y * 128;
    const int n0 = blockIdx.x * 64;
    const int wm = (wid & 1) * 64;
    const int wn = (wid >> 1) * 32;

    const uint32_t ld_sw = SWZ(((tid >> 3) << 7) + ((tid & 7) << 4));
    const __half* srcA = A + (size_t)(m0 + (tid >> 3)) * CC + (tid & 7) * 8;
    const __half* srcB = B + (size_t)(n0 + (tid >> 3)) * CC + (tid & 7) * 8;

    uint32_t a_off[4][4], b_off[2][4];
    #pragma unroll
    for (int mi = 0; mi < 4; ++mi)
        #pragma unroll
        for (int s = 0; s < 4; ++s) {
            const int r = wm + mi * 16 + (lid & 15);
            const int cb = s * 32 + ((lid >> 4) << 4);
            a_off[mi][s] = SWZ(r * 128 + cb);
        }
    #pragma unroll
    for (int pr = 0; pr < 2; ++pr)
        #pragma unroll
        for (int s = 0; s < 4; ++s) {
            const int r = wn + pr * 16 + (lid & 7) + ((lid >> 4) << 3);
            const int cb = s * 32 + (((lid >> 3) & 1) << 4);
            b_off[pr][s] = SWZ(r * 128 + cb);
        }

    float acc[4][4][4];
    #pragma unroll
    for (int i = 0; i < 4; ++i)
        #pragma unroll
        for (int j = 0; j < 4; ++j)
            #pragma unroll
            for (int e = 0; e < 4; ++e) acc[i][j][e] = 0.f;

    auto issue = [&](int ch, int stage) {
        const uint32_t so = sbase + stage * STG_BYTES + ld_sw;
        const __half* sa = srcA + ch * KC;
        const __half* sb2 = srcB + ch * KC;
        #pragma unroll
        for (int it = 0; it < 8; ++it)
            CP_ASYNC16(so + it * 2048, sa + it * 16 * CC);
        #pragma unroll
        for (int it = 0; it < 4; ++it)
            CP_ASYNC16(so + STG_A + it * 2048, sb2 + it * 16 * CC);
        CP_COMMIT();
    };

    issue(0, 0);

    for (int ch = 0; ch < NCH; ++ch) {
        if (ch + 1 < NCH) {
            issue(ch + 1, (ch + 1) & 1);
            CP_WAIT1();
        } else {
            CP_WAIT0();
        }
        __syncthreads();

        const uint32_t Ab = sbase + (ch & 1) * STG_BYTES;
        const uint32_t Bb = Ab + STG_A;

        #pragma unroll
        for (int s = 0; s < 4; ++s) {
            uint32_t ah[4][4];
            #pragma unroll
            for (int mi = 0; mi < 4; ++mi)
                LDM_X4(ah[mi][0], ah[mi][1], ah[mi][2], ah[mi][3], Ab + a_off[mi][s]);
            #pragma unroll
            for (int pr = 0; pr < 2; ++pr) {
                uint32_t b0, b1, b2, b3;
                LDM_X4(b0, b1, b2, b3, Bb + b_off[pr][s]);
                #pragma unroll
                for (int mi = 0; mi < 4; ++mi) {
                    MMA_F16(acc[mi][2 * pr + 0], ah[mi], b0, b1);
                    MMA_F16(acc[mi][2 * pr + 1], ah[mi], b2, b3);
                }
            }
        }
        __syncthreads();
    }

    #pragma unroll
    for (int nj = 0; nj < 4; ++nj) {
        const int n = n0 + wn + nj * 8 + (lid & 3) * 2;
        const float bx = bias[n], by = bias[n + 1];
        #pragma unroll
        for (int mi = 0; mi < 4; ++mi) {
            #pragma unroll
            for (int half = 0; half < 2; ++half) {
                const int m = m0 + wm + mi * 16 + (lid >> 2) + half * 8;
                const float rx = (acc[mi][nj][2 * half + 0] + bx) * scale;
                const float ry = (acc[mi][nj][2 * half + 1] + by) * scale;
                if (MODE == 0) {
                    float2 r; r.x = rx; r.y = ry;
                    *(float2*)(outF + (size_t)m * CC + n) = r;
                } else {
                    const int b = m >> 11, t = m & (TT - 1);
                    const int h = n >> 6, d = n & 63;
                    const size_t idx = (((size_t)b * HH + h) * TT + t) * DD + d;
                    *(uint32_t*)(outH + idx) = pack_h2(rx, ry);
                }
            }
        }
    }
}

// QKV fused: blockIdx.z selects projection. Q pre-scaled by log2e/8 so the
// attention softmax can run in the exp2 domain.
#define QSCALE 0.1803368801111204f   // log2(e) / 8

__global__ void __launch_bounds__(128, 4) qkv_gemm(
    const __half* __restrict__ x,
    const __half* __restrict__ wq, const __half* __restrict__ wk,
    const __half* __restrict__ wv,
    const float* __restrict__ bq, const float* __restrict__ bk,
    const float* __restrict__ bv,
    __half* __restrict__ q, __half* __restrict__ k, __half* __restrict__ v)
{
    extern __shared__ char smem[];
    const int z = blockIdx.z;
    const __half* B = (z == 0) ? wq : (z == 1) ? wk : wv;
    const float* bias = (z == 0) ? bq : (z == 1) ? bk : bv;
    __half* o = (z == 0) ? q : (z == 1) ? k : v;
    const float scale = (z == 0) ? QSCALE : 1.0f;
    gemm_core<1>(smem, x, B, bias, nullptr, o, scale);
}

__global__ void __launch_bounds__(128, 4) proj_gemm(
    const __half* __restrict__ y, const __half* __restrict__ wp,
    const float* __restrict__ bp, float* __restrict__ out)
{
    extern __shared__ char smem[];
    gemm_core<0>(smem, y, wp, bp, out, nullptr, 1.0f);
}

// ---------------------------------------------------------------------------
// Flash attention, fp16 mma.sync, exp2-domain fp32 softmax.
// CTA: 64 q-rows of one (b,h); 128 threads = 4 warps x 16 rows; kv tiles 64.
// SMEM: Q 8K | stage{0,1}: K 8K, V 8K => 40K total -> 4 CTAs/SM.
// Every warp computes every tile of its loop (no diagonal idling).
// ---------------------------------------------------------------------------
#define ATT_STG 16384
#define ATT_SMEM (8192 + 2 * ATT_STG)   // 40960

__global__ void __launch_bounds__(128, 4) attn_mma(
    const __half* __restrict__ q, const __half* __restrict__ k,
    const __half* __restrict__ v, __half* __restrict__ y)
{
    extern __shared__ char smem[];
    const uint32_t sb = smem_u32(smem);
    const int tid = threadIdx.x;
    const int wid = tid >> 5;
    const int lid = tid & 31;
    const int qt0 = blockIdx.x * 64;
    const int bh = blockIdx.y;
    const int wm = wid * 16;
    const size_t hb = (size_t)bh * TT * DD;

    const __half* kp = k + hb;
    const __half* vp = v + hb;

    // Q tile: 64 rows * 128B = 512 16B units, 4 per thread
    #pragma unroll
    for (int it = 0; it < 4; ++it) {
        const int u = (it << 7) + tid;
        const int r = u >> 3, c = u & 7;
        CP_ASYNC16(sb + SWZ(r * 128 + c * 16),
                   q + hb + (size_t)(qt0 + r) * DD + c * 8);
    }
    CP_COMMIT();

    const int ntiles = blockIdx.x + 1;

    auto issue_kv = [&](int t, int stage) {
        const int kt0 = t * 64;
        #pragma unroll
        for (int it = 0; it < 8; ++it) {
            const int arr = it >> 2;              // 0=K, 1=V
            const int u = ((it & 3) << 7) + tid;  // 0..511
            const int r = u >> 3, c = u & 7;
            const __half* p = arr ? vp : kp;
            CP_ASYNC16(sb + 8192 + stage * ATT_STG + arr * 8192 + SWZ(r * 128 + c * 16),
                       p + (size_t)(kt0 + r) * DD + c * 8);
        }
        CP_COMMIT();
    };

    issue_kv(0, 0);
    CP_WAIT1();
    __syncthreads();

    // Q fragments held in registers for whole kernel
    uint32_t aq[4][4];
    {
        const int ar = wm + (lid & 15);
        const int ac = (lid >> 4) << 4;
        #pragma unroll
        for (int s = 0; s < 4; ++s) {
            const uint32_t off = SWZ(ar * 128 + s * 32 + ac);
            LDM_X4(aq[s][0], aq[s][1], aq[s][2], aq[s][3], sb + off);
        }
    }

    const int brow = (lid & 7) + ((lid >> 4) << 3);
    const int bcol = ((lid >> 3) & 1) << 4;
    const int vrow = (lid & 7) + (((lid >> 3) & 1) << 3);
    const int vcol = (lid >> 4) << 4;

    float oacc[8][4];
    #pragma unroll
    for (int j = 0; j < 8; ++j)
        #pragma unroll
        for (int e = 0; e < 4; ++e) oacc[j][e] = 0.f;
    float m0 = -1e30f, m1 = -1e30f, l0 = 0.f, l1 = 0.f;

    const int row0 = qt0 + wm + (lid >> 2);
    const int row1 = row0 + 8;
    const int colb = 2 * (lid & 3);

    for (int t = 0; t < ntiles; ++t) {
        if (t + 1 < ntiles) { issue_kv(t + 1, (t + 1) & 1); CP_WAIT1(); }
        else CP_WAIT0();
        __syncthreads();

        const int kt0 = t * 64;
        {
            const uint32_t stg = sb + 8192 + (t & 1) * ATT_STG;
            const uint32_t kB = stg, vB = stg + 8192;

            // ---- S = Q K^T (scores already in log2 domain) ----
            float sacc[8][4];
            #pragma unroll
            for (int j = 0; j < 8; ++j)
                #pragma unroll
                for (int e = 0; e < 4; ++e) sacc[j][e] = 0.f;

            #pragma unroll
            for (int s = 0; s < 4; ++s) {
                #pragma unroll
                for (int pr = 0; pr < 4; ++pr) {
                    const uint32_t boff = SWZ((pr * 16 + brow) * 128 + s * 32 + bcol);
                    uint32_t b0, b1, b2, b3;
                    LDM_X4(b0, b1, b2, b3, kB + boff);
                    MMA_F16(sacc[2 * pr + 0], aq[s], b0, b1);
                    MMA_F16(sacc[2 * pr + 1], aq[s], b2, b3);
                }
            }

            // ---- causal mask (diagonal tile only) ----
            if (kt0 + 64 > qt0 + wm) {
                #pragma unroll
                for (int j = 0; j < 8; ++j) {
                    const int c0 = kt0 + j * 8 + colb;
                    if (c0 > row0)     sacc[j][0] = -1e30f;
                    if (c0 + 1 > row0) sacc[j][1] = -1e30f;
                    if (c0 > row1)     sacc[j][2] = -1e30f;
                    if (c0 + 1 > row1) sacc[j][3] = -1e30f;
                }
            }

            // ---- online softmax (exp2 domain) ----
            float mx0 = -1e30f, mx1 = -1e30f;
            #pragma unroll
            for (int j = 0; j < 8; ++j) {
                mx0 = fmaxf(mx0, fmaxf(sacc[j][0], sacc[j][1]));
                mx1 = fmaxf(mx1, fmaxf(sacc[j][2], sacc[j][3]));
            }
            mx0 = fmaxf(mx0, __shfl_xor_sync(0xffffffffu, mx0, 1));
            mx0 = fmaxf(mx0, __shfl_xor_sync(0xffffffffu, mx0, 2));
            mx1 = fmaxf(mx1, __shfl_xor_sync(0xffffffffu, mx1, 1));
            mx1 = fmaxf(mx1, __shfl_xor_sync(0xffffffffu, mx1, 2));
            const float mn0 = fmaxf(m0, mx0), mn1 = fmaxf(m1, mx1);
            const float al0 = ex2f(m0 - mn0), al1 = ex2f(m1 - mn1);
            m0 = mn0; m1 = mn1;

            float rs0 = 0.f, rs1 = 0.f;
            #pragma unroll
            for (int j = 0; j < 8; ++j) {
                sacc[j][0] = ex2f(sacc[j][0] - m0);
                sacc[j][1] = ex2f(sacc[j][1] - m0);
                sacc[j][2] = ex2f(sacc[j][2] - m1);
                sacc[j][3] = ex2f(sacc[j][3] - m1);
                rs0 += sacc[j][0] + sacc[j][1];
                rs1 += sacc[j][2] + sacc[j][3];
            }
            rs0 += __shfl_xor_sync(0xffffffffu, rs0, 1);
            rs0 += __shfl_xor_sync(0xffffffffu, rs0, 2);
            rs1 += __shfl_xor_sync(0xffffffffu, rs1, 1);
            rs1 += __shfl_xor_sync(0xffffffffu, rs1, 2);
            l0 = l0 * al0 + rs0;
            l1 = l1 * al1 + rs1;
            #pragma unroll
            for (int j = 0; j < 8; ++j) {
                oacc[j][0] *= al0; oacc[j][1] *= al0;
                oacc[j][2] *= al1; oacc[j][3] *= al1;
            }

            // ---- O += P V ----
            #pragma unroll
            for (int kk = 0; kk < 4; ++kk) {
                const int j0 = 2 * kk, j1 = j0 + 1;
                uint32_t ph[4];
                ph[0] = pack_h2(sacc[j0][0], sacc[j0][1]);
                ph[1] = pack_h2(sacc[j0][2], sacc[j0][3]);
                ph[2] = pack_h2(sacc[j1][0], sacc[j1][1]);
                ph[3] = pack_h2(sacc[j1][2], sacc[j1][3]);
                #pragma unroll
                for (int dd = 0; dd < 4; ++dd) {
                    const uint32_t voff = SWZ((kk * 16 + vrow) * 128 + dd * 32 + vcol);
                    uint32_t v0, v1, v2, v3;
                    LDM_X4T(v0, v1, v2, v3, vB + voff);
                    MMA_F16(oacc[2 * dd + 0], ph, v0, v1);
                    MMA_F16(oacc[2 * dd + 1], ph, v2, v3);
                }
            }
        }
        __syncthreads();
    }

    // ---- epilogue: normalize, write (b,t,c) fp16 ----
    const int b = bh >> 4, h = bh & 15;
    const float inv0 = 1.f / l0, inv1 = 1.f / l1;
    #pragma unroll
    for (int j = 0; j < 8; ++j) {
        const int d = j * 8 + colb;
        const size_t i0 = ((size_t)b * TT + row0) * CC + h * DD + d;
        const size_t i1 = ((size_t)b * TT + row1) * CC + h * DD + d;
        *(uint32_t*)(y + i0) = pack_h2(oacc[j][0] * inv0, oacc[j][1] * inv0);
        *(uint32_t*)(y + i1) = pack_h2(oacc[j][2] * inv1, oacc[j][3] * inv1);
    }
}

// ---------------------------------------------------------------------------
// Launch
// ---------------------------------------------------------------------------
extern "C" void kernel_launch(void* const* d_in, const int* in_sizes, int n_in,
                              void* d_out, int out_size)
{
    (void)in_sizes; (void)n_in; (void)out_size;
    const float* x  = (const float*)d_in[0];
    const float* Wk = (const float*)d_in[1];
    const float* bk = (const float*)d_in[2];
    const float* Wq = (const float*)d_in[3];
    const float* bq = (const float*)d_in[4];
    const float* Wv = (const float*)d_in[5];
    const float* bv = (const float*)d_in[6];
    const float* Wp = (const float*)d_in[7];
    const float* bp = (const float*)d_in[8];
    float* out = (float*)d_out;

    __half *px, *pq, *pk, *pv, *py, *pwq, *pwk, *pwv, *pwp;
    cudaGetSymbolAddress((void**)&px, g_x);
    cudaGetSymbolAddress((void**)&pq, g_q);
    cudaGetSymbolAddress((void**)&pk, g_k);
    cudaGetSymbolAddress((void**)&pv, g_v);
    cudaGetSymbolAddress((void**)&py, g_y);
    cudaGetSymbolAddress((void**)&pwq, g_wq);
    cudaGetSymbolAddress((void**)&pwk, g_wk);
    cudaGetSymbolAddress((void**)&pwv, g_wv);
    cudaGetSymbolAddress((void**)&pwp, g_wp);

    cvt_all<<<(XN4 + 4 * WN4 + 255) / 256, 256>>>(
        x, Wq, Wk, Wv, Wp, px, pwq, pwk, pwv, pwp);

    cudaFuncSetAttribute(qkv_gemm, cudaFuncAttributeMaxDynamicSharedMemorySize, GEMM_SMEM);
    cudaFuncSetAttribute(proj_gemm, cudaFuncAttributeMaxDynamicSharedMemorySize, GEMM_SMEM);
    cudaFuncSetAttribute(attn_mma, cudaFuncAttributeMaxDynamicSharedMemorySize, ATT_SMEM);

    qkv_gemm<<<dim3(CC / 64, MM / 128, 3), 128, GEMM_SMEM>>>(
        px, pwq, pwk, pwv, bq, bk, bv, pq, pk, pv);

    attn_mma<<<dim3(TT / 64, BB * HH), 128, ATT_SMEM>>>(pq, pk, pv, py);

    proj_gemm<<<dim3(CC / 64, MM / 128), 128, GEMM_SMEM>>>(py, pwp, bp, out);
}

// round 17
// speedup vs baseline: 4.5281x; 1.0078x over previous
#include <cuda_runtime.h>
#include <cuda_fp16.h>
#include <math.h>
#include <stdint.h>

// Problem constants
#define BB 4
#define TT 2048
#define CC 1024
#define HH 16
#define DD 64
#define MM (BB*TT)   // 8192 rows

// ---------------------------------------------------------------------------
// Scratch (__device__ globals; no allocation allowed) — all fp16
// ---------------------------------------------------------------------------
__device__ __half g_x[(size_t)MM * CC];
__device__ __half g_q[(size_t)MM * CC];   // (b,h,t,d), pre-scaled by log2e/8
__device__ __half g_k[(size_t)MM * CC];
__device__ __half g_v[(size_t)MM * CC];
__device__ __half g_y[(size_t)MM * CC];   // (b,t,c)
__device__ __half g_wq[(size_t)CC * CC];
__device__ __half g_wk[(size_t)CC * CC];
__device__ __half g_wv[(size_t)CC * CC];
__device__ __half g_wp[(size_t)CC * CC];

// ---------------------------------------------------------------------------
// Helpers (baseline PTX only)
// ---------------------------------------------------------------------------
__device__ __forceinline__ uint32_t smem_u32(const void* p) {
    uint32_t a;
    asm("{ .reg .u64 t; cvta.to.shared.u64 t, %1; cvt.u32.u64 %0, t; }" : "=r"(a) : "l"(p));
    return a;
}
#define CP_ASYNC16(dst, src) \
    asm volatile("cp.async.cg.shared.global [%0], [%1], 16;" :: "r"(dst), "l"(src) : "memory")
#define CP_COMMIT() asm volatile("cp.async.commit_group;" ::: "memory")
#define CP_WAIT0()  asm volatile("cp.async.wait_group 0;" ::: "memory")
#define CP_WAIT1()  asm volatile("cp.async.wait_group 1;" ::: "memory")

#define LDM_X4(r0, r1, r2, r3, a) \
    asm volatile("ldmatrix.sync.aligned.m8n8.x4.shared.b16 {%0,%1,%2,%3}, [%4];" \
        : "=r"(r0), "=r"(r1), "=r"(r2), "=r"(r3) : "r"(a))
#define LDM_X4T(r0, r1, r2, r3, a) \
    asm volatile("ldmatrix.sync.aligned.m8n8.x4.trans.shared.b16 {%0,%1,%2,%3}, [%4];" \
        : "=r"(r0), "=r"(r1), "=r"(r2), "=r"(r3) : "r"(a))

#define MMA_F16(acc, a, b0, b1) \
    asm volatile("mma.sync.aligned.m16n8k16.row.col.f32.f16.f16.f32 " \
        "{%0,%1,%2,%3},{%4,%5,%6,%7},{%8,%9},{%0,%1,%2,%3};" \
        : "+f"((acc)[0]), "+f"((acc)[1]), "+f"((acc)[2]), "+f"((acc)[3]) \
        : "r"((a)[0]), "r"((a)[1]), "r"((a)[2]), "r"((a)[3]), "r"(b0), "r"(b1))

#define SWZ(x) ((x) ^ (((x) >> 3) & 0x70))

__device__ __forceinline__ uint32_t pack_h2(float x, float y) {
    __half2 h = __floats2half2_rn(x, y);
    return *(uint32_t*)&h;
}
__device__ __forceinline__ float ex2f(float x) {
    float r;
    asm("ex2.approx.f32 %0, %1;" : "=f"(r) : "f"(x));
    return r;
}
__device__ __forceinline__ uint32_t ex2_h2(uint32_t x) {
    uint32_t r;
    asm("ex2.approx.f16x2 %0, %1;" : "=r"(r) : "r"(x));
    return r;
}

// ---------------------------------------------------------------------------
// Fused fp32 -> fp16 conversion for x + 4 weight matrices.
// ---------------------------------------------------------------------------
#define XN4 (MM * CC / 4)
#define WN4 (CC * CC / 4)

__global__ void __launch_bounds__(256) cvt_all(
    const float* __restrict__ x,
    const float* __restrict__ Wq, const float* __restrict__ Wk,
    const float* __restrict__ Wv, const float* __restrict__ Wp,
    __half* __restrict__ xo,
    __half* __restrict__ wqo, __half* __restrict__ wko,
    __half* __restrict__ wvo, __half* __restrict__ wpo)
{
    int i = blockIdx.x * blockDim.x + threadIdx.x;
    const float* src;
    __half* dst;
    int off;
    if (i < XN4) { src = x; dst = xo; off = i; }
    else {
        int j = i - XN4;
        const int w = j / WN4;
        off = j - w * WN4;
        if (w == 0)      { src = Wq; dst = wqo; }
        else if (w == 1) { src = Wk; dst = wko; }
        else if (w == 2) { src = Wv; dst = wvo; }
        else             { src = Wp; dst = wpo; }
    }
    float4 v = ((const float4*)src)[off];
    ((__half2*)dst)[2 * off + 0] = __floats2half2_rn(v.x, v.y);
    ((__half2*)dst)[2 * off + 1] = __floats2half2_rn(v.z, v.w);
}

// ---------------------------------------------------------------------------
// mma.sync fp16 GEMM (unchanged — 63.3% tensor, protect it).
// CTA tile 128x64, 128 threads = 4 warps (2m x 2n), warp tile 64x32.
// K-chunk 64, 2-stage cp.async, 4 CTAs/SM.
// ---------------------------------------------------------------------------
#define KC 64
#define NCH (CC / KC)        // 16
#define STG_A 16384
#define STG_B 8192
#define STG_BYTES (STG_A + STG_B)   // 24576
#define GEMM_SMEM (2 * STG_BYTES)   // 49152

template<int MODE>
__device__ __forceinline__ void gemm_core(
    char* smem,
    const __half* __restrict__ A, const __half* __restrict__ B,
    const float* __restrict__ bias, float* __restrict__ outF,
    __half* __restrict__ outH, float scale)
{
    const uint32_t sbase = smem_u32(smem);
    const int tid = threadIdx.x;
    const int wid = tid >> 5;
    const int lid = tid & 31;
    const int m0 = blockIdx.y * 128;
    const int n0 = blockIdx.x * 64;
    const int wm = (wid & 1) * 64;
    const int wn = (wid >> 1) * 32;

    const uint32_t ld_sw = SWZ(((tid >> 3) << 7) + ((tid & 7) << 4));
    const __half* srcA = A + (size_t)(m0 + (tid >> 3)) * CC + (tid & 7) * 8;
    const __half* srcB = B + (size_t)(n0 + (tid >> 3)) * CC + (tid & 7) * 8;

    uint32_t a_off[4][4], b_off[2][4];
    #pragma unroll
    for (int mi = 0; mi < 4; ++mi)
        #pragma unroll
        for (int s = 0; s < 4; ++s) {
            const int r = wm + mi * 16 + (lid & 15);
            const int cb = s * 32 + ((lid >> 4) << 4);
            a_off[mi][s] = SWZ(r * 128 + cb);
        }
    #pragma unroll
    for (int pr = 0; pr < 2; ++pr)
        #pragma unroll
        for (int s = 0; s < 4; ++s) {
            const int r = wn + pr * 16 + (lid & 7) + ((lid >> 4) << 3);
            const int cb = s * 32 + (((lid >> 3) & 1) << 4);
            b_off[pr][s] = SWZ(r * 128 + cb);
        }

    float acc[4][4][4];
    #pragma unroll
    for (int i = 0; i < 4; ++i)
        #pragma unroll
        for (int j = 0; j < 4; ++j)
            #pragma unroll
            for (int e = 0; e < 4; ++e) acc[i][j][e] = 0.f;

    auto issue = [&](int ch, int stage) {
        const uint32_t so = sbase + stage * STG_BYTES + ld_sw;
        const __half* sa = srcA + ch * KC;
        const __half* sb2 = srcB + ch * KC;
        #pragma unroll
        for (int it = 0; it < 8; ++it)
            CP_ASYNC16(so + it * 2048, sa + it * 16 * CC);
        #pragma unroll
        for (int it = 0; it < 4; ++it)
            CP_ASYNC16(so + STG_A + it * 2048, sb2 + it * 16 * CC);
        CP_COMMIT();
    };

    issue(0, 0);

    for (int ch = 0; ch < NCH; ++ch) {
        if (ch + 1 < NCH) {
            issue(ch + 1, (ch + 1) & 1);
            CP_WAIT1();
        } else {
            CP_WAIT0();
        }
        __syncthreads();

        const uint32_t Ab = sbase + (ch & 1) * STG_BYTES;
        const uint32_t Bb = Ab + STG_A;

        #pragma unroll
        for (int s = 0; s < 4; ++s) {
            uint32_t ah[4][4];
            #pragma unroll
            for (int mi = 0; mi < 4; ++mi)
                LDM_X4(ah[mi][0], ah[mi][1], ah[mi][2], ah[mi][3], Ab + a_off[mi][s]);
            #pragma unroll
            for (int pr = 0; pr < 2; ++pr) {
                uint32_t b0, b1, b2, b3;
                LDM_X4(b0, b1, b2, b3, Bb + b_off[pr][s]);
                #pragma unroll
                for (int mi = 0; mi < 4; ++mi) {
                    MMA_F16(acc[mi][2 * pr + 0], ah[mi], b0, b1);
                    MMA_F16(acc[mi][2 * pr + 1], ah[mi], b2, b3);
                }
            }
        }
        __syncthreads();
    }

    #pragma unroll
    for (int nj = 0; nj < 4; ++nj) {
        const int n = n0 + wn + nj * 8 + (lid & 3) * 2;
        const float bx = bias[n], by = bias[n + 1];
        #pragma unroll
        for (int mi = 0; mi < 4; ++mi) {
            #pragma unroll
            for (int half = 0; half < 2; ++half) {
                const int m = m0 + wm + mi * 16 + (lid >> 2) + half * 8;
                const float rx = (acc[mi][nj][2 * half + 0] + bx) * scale;
                const float ry = (acc[mi][nj][2 * half + 1] + by) * scale;
                if (MODE == 0) {
                    float2 r; r.x = rx; r.y = ry;
                    *(float2*)(outF + (size_t)m * CC + n) = r;
                } else {
                    const int b = m >> 11, t = m & (TT - 1);
                    const int h = n >> 6, d = n & 63;
                    const size_t idx = (((size_t)b * HH + h) * TT + t) * DD + d;
                    *(uint32_t*)(outH + idx) = pack_h2(rx, ry);
                }
            }
        }
    }
}

// QKV fused: blockIdx.z selects projection. Q pre-scaled by log2e/8 so the
// attention softmax can run in the exp2 domain.
#define QSCALE 0.1803368801111204f   // log2(e) / 8

__global__ void __launch_bounds__(128, 4) qkv_gemm(
    const __half* __restrict__ x,
    const __half* __restrict__ wq, const __half* __restrict__ wk,
    const __half* __restrict__ wv,
    const float* __restrict__ bq, const float* __restrict__ bk,
    const float* __restrict__ bv,
    __half* __restrict__ q, __half* __restrict__ k, __half* __restrict__ v)
{
    extern __shared__ char smem[];
    const int z = blockIdx.z;
    const __half* B = (z == 0) ? wq : (z == 1) ? wk : wv;
    const float* bias = (z == 0) ? bq : (z == 1) ? bk : bv;
    __half* o = (z == 0) ? q : (z == 1) ? k : v;
    const float scale = (z == 0) ? QSCALE : 1.0f;
    gemm_core<1>(smem, x, B, bias, nullptr, o, scale);
}

__global__ void __launch_bounds__(128, 4) proj_gemm(
    const __half* __restrict__ y, const __half* __restrict__ wp,
    const float* __restrict__ bp, float* __restrict__ out)
{
    extern __shared__ char smem[];
    gemm_core<0>(smem, y, wp, bp, out, nullptr, 1.0f);
}

// ---------------------------------------------------------------------------
// Flash attention, fp16 mma.sync, exp2-domain softmax with f16x2 MUFU.
// CTA: 64 q-rows of one (b,h); 128 threads = 4 warps x 16 rows; kv tiles 64.
// SMEM: Q 8K | stage{0,1}: K 8K, V 8K => 40K total -> 4 CTAs/SM.
// q-tile index REVERSED so longest CTAs launch first (kills diagonal tail).
// ---------------------------------------------------------------------------
#define ATT_STG 16384
#define ATT_SMEM (8192 + 2 * ATT_STG)   // 40960

__global__ void __launch_bounds__(128, 4) attn_mma(
    const __half* __restrict__ q, const __half* __restrict__ k,
    const __half* __restrict__ v, __half* __restrict__ y)
{
    extern __shared__ char smem[];
    const uint32_t sb = smem_u32(smem);
    const int tid = threadIdx.x;
    const int wid = tid >> 5;
    const int lid = tid & 31;
    const int qtile = gridDim.x - 1 - blockIdx.x;   // longest-first
    const int qt0 = qtile * 64;
    const int bh = blockIdx.y;
    const int wm = wid * 16;
    const size_t hb = (size_t)bh * TT * DD;

    const __half* kp = k + hb;
    const __half* vp = v + hb;

    // Q tile: 64 rows * 128B = 512 16B units, 4 per thread
    #pragma unroll
    for (int it = 0; it < 4; ++it) {
        const int u = (it << 7) + tid;
        const int r = u >> 3, c = u & 7;
        CP_ASYNC16(sb + SWZ(r * 128 + c * 16),
                   q + hb + (size_t)(qt0 + r) * DD + c * 8);
    }
    CP_COMMIT();

    const int ntiles = qtile + 1;

    auto issue_kv = [&](int t, int stage) {
        const int kt0 = t * 64;
        #pragma unroll
        for (int it = 0; it < 8; ++it) {
            const int arr = it >> 2;              // 0=K, 1=V
            const int u = ((it & 3) << 7) + tid;  // 0..511
            const int r = u >> 3, c = u & 7;
            const __half* p = arr ? vp : kp;
            CP_ASYNC16(sb + 8192 + stage * ATT_STG + arr * 8192 + SWZ(r * 128 + c * 16),
                       p + (size_t)(kt0 + r) * DD + c * 8);
        }
        CP_COMMIT();
    };

    issue_kv(0, 0);
    CP_WAIT1();
    __syncthreads();

    // Q fragments held in registers for whole kernel
    uint32_t aq[4][4];
    {
        const int ar = wm + (lid & 15);
        const int ac = (lid >> 4) << 4;
        #pragma unroll
        for (int s = 0; s < 4; ++s) {
            const uint32_t off = SWZ(ar * 128 + s * 32 + ac);
            LDM_X4(aq[s][0], aq[s][1], aq[s][2], aq[s][3], sb + off);
        }
    }

    const int brow = (lid & 7) + ((lid >> 4) << 3);
    const int bcol = ((lid >> 3) & 1) << 4;
    const int vrow = (lid & 7) + (((lid >> 3) & 1) << 3);
    const int vcol = (lid >> 4) << 4;

    float oacc[8][4];
    #pragma unroll
    for (int j = 0; j < 8; ++j)
        #pragma unroll
        for (int e = 0; e < 4; ++e) oacc[j][e] = 0.f;
    float m0 = -1e30f, m1 = -1e30f, l0 = 0.f, l1 = 0.f;

    const int row0 = qt0 + wm + (lid >> 2);
    const int row1 = row0 + 8;
    const int colb = 2 * (lid & 3);

    for (int t = 0; t < ntiles; ++t) {
        if (t + 1 < ntiles) { issue_kv(t + 1, (t + 1) & 1); CP_WAIT1(); }
        else CP_WAIT0();
        __syncthreads();

        const int kt0 = t * 64;
        {
            const uint32_t stg = sb + 8192 + (t & 1) * ATT_STG;
            const uint32_t kB = stg, vB = stg + 8192;

            // ---- S = Q K^T (scores already in log2 domain) ----
            float sacc[8][4];
            #pragma unroll
            for (int j = 0; j < 8; ++j)
                #pragma unroll
                for (int e = 0; e < 4; ++e) sacc[j][e] = 0.f;

            #pragma unroll
            for (int s = 0; s < 4; ++s) {
                #pragma unroll
                for (int pr = 0; pr < 4; ++pr) {
                    const uint32_t boff = SWZ((pr * 16 + brow) * 128 + s * 32 + bcol);
                    uint32_t b0, b1, b2, b3;
                    LDM_X4(b0, b1, b2, b3, kB + boff);
                    MMA_F16(sacc[2 * pr + 0], aq[s], b0, b1);
                    MMA_F16(sacc[2 * pr + 1], aq[s], b2, b3);
                }
            }

            // ---- causal mask (diagonal tile only) ----
            if (kt0 + 64 > qt0 + wm) {
                #pragma unroll
                for (int j = 0; j < 8; ++j) {
                    const int c0 = kt0 + j * 8 + colb;
                    if (c0 > row0)     sacc[j][0] = -1e30f;
                    if (c0 + 1 > row0) sacc[j][1] = -1e30f;
                    if (c0 > row1)     sacc[j][2] = -1e30f;
                    if (c0 + 1 > row1) sacc[j][3] = -1e30f;
                }
            }

            // ---- online softmax (exp2 domain, f16x2 MUFU) ----
            float mx0 = -1e30f, mx1 = -1e30f;
            #pragma unroll
            for (int j = 0; j < 8; ++j) {
                mx0 = fmaxf(mx0, fmaxf(sacc[j][0], sacc[j][1]));
                mx1 = fmaxf(mx1, fmaxf(sacc[j][2], sacc[j][3]));
            }
            mx0 = fmaxf(mx0, __shfl_xor_sync(0xffffffffu, mx0, 1));
            mx0 = fmaxf(mx0, __shfl_xor_sync(0xffffffffu, mx0, 2));
            mx1 = fmaxf(mx1, __shfl_xor_sync(0xffffffffu, mx1, 1));
            mx1 = fmaxf(mx1, __shfl_xor_sync(0xffffffffu, mx1, 2));
            const float mn0 = fmaxf(m0, mx0), mn1 = fmaxf(m1, mx1);
            const float al0 = ex2f(m0 - mn0), al1 = ex2f(m1 - mn1);
            m0 = mn0; m1 = mn1;

            // exp in packed-half domain: P fragments produced directly.
            uint32_t pfrag[8][2];
            float rs0 = 0.f, rs1 = 0.f;
            #pragma unroll
            for (int j = 0; j < 8; ++j) {
                const uint32_t e0 = ex2_h2(pack_h2(sacc[j][0] - m0, sacc[j][1] - m0));
                const uint32_t e1 = ex2_h2(pack_h2(sacc[j][2] - m1, sacc[j][3] - m1));
                pfrag[j][0] = e0;
                pfrag[j][1] = e1;
                const float2 f0 = __half22float2(*(const __half2*)&e0);
                const float2 f1 = __half22float2(*(const __half2*)&e1);
                rs0 += f0.x + f0.y;
                rs1 += f1.x + f1.y;
            }
            rs0 += __shfl_xor_sync(0xffffffffu, rs0, 1);
            rs0 += __shfl_xor_sync(0xffffffffu, rs0, 2);
            rs1 += __shfl_xor_sync(0xffffffffu, rs1, 1);
            rs1 += __shfl_xor_sync(0xffffffffu, rs1, 2);
            l0 = l0 * al0 + rs0;
            l1 = l1 * al1 + rs1;
            #pragma unroll
            for (int j = 0; j < 8; ++j) {
                oacc[j][0] *= al0; oacc[j][1] *= al0;
                oacc[j][2] *= al1; oacc[j][3] *= al1;
            }

            // ---- O += P V ----
            #pragma unroll
            for (int kk = 0; kk < 4; ++kk) {
                uint32_t ph[4];
                ph[0] = pfrag[2 * kk + 0][0];
                ph[1] = pfrag[2 * kk + 0][1];
                ph[2] = pfrag[2 * kk + 1][0];
                ph[3] = pfrag[2 * kk + 1][1];
                #pragma unroll
                for (int dd = 0; dd < 4; ++dd) {
                    const uint32_t voff = SWZ((kk * 16 + vrow) * 128 + dd * 32 + vcol);
                    uint32_t v0, v1, v2, v3;
                    LDM_X4T(v0, v1, v2, v3, vB + voff);
                    MMA_F16(oacc[2 * dd + 0], ph, v0, v1);
                    MMA_F16(oacc[2 * dd + 1], ph, v2, v3);
                }
            }
        }
        __syncthreads();
    }

    // ---- epilogue: normalize, write (b,t,c) fp16 ----
    const int b = bh >> 4, h = bh & 15;
    const float inv0 = 1.f / l0, inv1 = 1.f / l1;
    #pragma unroll
    for (int j = 0; j < 8; ++j) {
        const int d = j * 8 + colb;
        const size_t i0 = ((size_t)b * TT + row0) * CC + h * DD + d;
        const size_t i1 = ((size_t)b * TT + row1) * CC + h * DD + d;
        *(uint32_t*)(y + i0) = pack_h2(oacc[j][0] * inv0, oacc[j][1] * inv0);
        *(uint32_t*)(y + i1) = pack_h2(oacc[j][2] * inv1, oacc[j][3] * inv1);
    }
}

// ---------------------------------------------------------------------------
// Launch
// ---------------------------------------------------------------------------
extern "C" void kernel_launch(void* const* d_in, const int* in_sizes, int n_in,
                              void* d_out, int out_size)
{
    (void)in_sizes; (void)n_in; (void)out_size;
    const float* x  = (const float*)d_in[0];
    const float* Wk = (const float*)d_in[1];
    const float* bk = (const float*)d_in[2];
    const float* Wq = (const float*)d_in[3];
    const float* bq = (const float*)d_in[4];
    const float* Wv = (const float*)d_in[5];
    const float* bv = (const float*)d_in[6];
    const float* Wp = (const float*)d_in[7];
    const float* bp = (const float*)d_in[8];
    float* out = (float*)d_out;

    __half *px, *pq, *pk, *pv, *py, *pwq, *pwk, *pwv, *pwp;
    cudaGetSymbolAddress((void**)&px, g_x);
    cudaGetSymbolAddress((void**)&pq, g_q);
    cudaGetSymbolAddress((void**)&pk, g_k);
    cudaGetSymbolAddress((void**)&pv, g_v);
    cudaGetSymbolAddress((void**)&py, g_y);
    cudaGetSymbolAddress((void**)&pwq, g_wq);
    cudaGetSymbolAddress((void**)&pwk, g_wk);
    cudaGetSymbolAddress((void**)&pwv, g_wv);
    cudaGetSymbolAddress((void**)&pwp, g_wp);

    cvt_all<<<(XN4 + 4 * WN4 + 255) / 256, 256>>>(
        x, Wq, Wk, Wv, Wp, px, pwq, pwk, pwv, pwp);

    cudaFuncSetAttribute(qkv_gemm, cudaFuncAttributeMaxDynamicSharedMemorySize, GEMM_SMEM);
    cudaFuncSetAttribute(proj_gemm, cudaFuncAttributeMaxDynamicSharedMemorySize, GEMM_SMEM);
    cudaFuncSetAttribute(attn_mma, cudaFuncAttributeMaxDynamicSharedMemorySize, ATT_SMEM);

    qkv_gemm<<<dim3(CC / 64, MM / 128, 3), 128, GEMM_SMEM>>>(
        px, pwq, pwk, pwv, bq, bk, bv, pq, pk, pv);

    attn_mma<<<dim3(TT / 64, BB * HH), 128, ATT_SMEM>>>(pq, pk, pv, py);

    proj_gemm<<<dim3(CC / 64, MM / 128), 128, GEMM_SMEM>>>(py, pwp, bp, out);
}